// round 5
// baseline (speedup 1.0000x reference)
#include <cuda_runtime.h>
#include <cuda_bf16.h>
#include <math.h>
#include <stdint.h>

// Problem constants
#define Bv 2
#define Sv 2048
#define Dv 1024
#define Hv 16
#define HDv 64
#define Mv (Bv*Sv)   // 4096 rows

// ---------------------------------------------------------------------------
// Scratch (device globals: no allocation allowed)
// ---------------------------------------------------------------------------
__device__ __align__(16) __nv_bfloat16 g_xh[(size_t)Mv * Dv];
__device__ __align__(16) __nv_bfloat16 g_xl[(size_t)Mv * Dv];
__device__ __align__(16) __nv_bfloat16 g_wqh[(size_t)3 * Dv * Dv];
__device__ __align__(16) __nv_bfloat16 g_wql[(size_t)3 * Dv * Dv];
__device__ __align__(16) __nv_bfloat16 g_qkvh[(size_t)Mv * 3 * Dv];
__device__ __align__(16) __nv_bfloat16 g_qkvl[(size_t)Mv * 3 * Dv];
__device__ __align__(16) __nv_bfloat16 g_oh[(size_t)Mv * Dv];
__device__ __align__(16) __nv_bfloat16 g_ol[(size_t)Mv * Dv];
__device__ __align__(16) __nv_bfloat16 g_woh[(size_t)Dv * Dv];
__device__ __align__(16) __nv_bfloat16 g_wol[(size_t)Dv * Dv];

// ---------------------------------------------------------------------------
// PTX helpers
// ---------------------------------------------------------------------------
__device__ __forceinline__ uint32_t smem_u32(const void* p) {
    uint32_t a;
    asm("{ .reg .u64 t; cvta.to.shared.u64 t, %1; cvt.u32.u64 %0, t; }" : "=r"(a) : "l"(p));
    return a;
}
#define CP_ASYNC16(sm, g) \
    asm volatile("cp.async.cg.shared.global [%0], [%1], 16;" :: "r"(sm), "l"(g) : "memory")
#define CP_COMMIT() asm volatile("cp.async.commit_group;" ::: "memory")
#define CP_WAIT(n)  asm volatile("cp.async.wait_group %0;" :: "n"(n) : "memory")

#define LDSM_X4(r0, r1, r2, r3, addr) \
    asm volatile("ldmatrix.sync.aligned.m8n8.x4.shared.b16 {%0,%1,%2,%3}, [%4];" \
        : "=r"(r0), "=r"(r1), "=r"(r2), "=r"(r3) : "r"(addr))
#define LDSM_X4_T(r0, r1, r2, r3, addr) \
    asm volatile("ldmatrix.sync.aligned.m8n8.x4.trans.shared.b16 {%0,%1,%2,%3}, [%4];" \
        : "=r"(r0), "=r"(r1), "=r"(r2), "=r"(r3) : "r"(addr))

#define MMA16816(d, a, b) \
    asm volatile("mma.sync.aligned.m16n8k16.row.col.f32.bf16.bf16.f32 " \
        "{%0,%1,%2,%3}, {%4,%5,%6,%7}, {%8,%9}, {%0,%1,%2,%3};" \
        : "+f"((d)[0]), "+f"((d)[1]), "+f"((d)[2]), "+f"((d)[3]) \
        : "r"((a)[0]), "r"((a)[1]), "r"((a)[2]), "r"((a)[3]), "r"((b)[0]), "r"((b)[1]))

// pack(lo, hi) -> bf16x2 register (hi in upper 16 bits)
__device__ __forceinline__ uint32_t packbf(float lo, float hi) {
    uint32_t r;
    asm("cvt.rn.bf16x2.f32 %0, %1, %2;" : "=r"(r) : "f"(hi), "f"(lo));
    return r;
}
// residual of a prior packbf
__device__ __forceinline__ uint32_t packres(uint32_t h, float lo, float hi) {
    float lof = __uint_as_float(h << 16);
    float hif = __uint_as_float(h & 0xFFFF0000u);
    return packbf(lo - lof, hi - hif);
}

// ---------------------------------------------------------------------------
// fp32 -> (bf16 hi, bf16 lo) split kernel
// ---------------------------------------------------------------------------
__global__ __launch_bounds__(256) void split_bf16(
    const float* __restrict__ in, __nv_bfloat16* __restrict__ hi,
    __nv_bfloat16* __restrict__ lo, int n4)
{
    int i = blockIdx.x * blockDim.x + threadIdx.x;
    if (i >= n4) return;
    float4 v = ((const float4*)in)[i];
    uint32_t h0 = packbf(v.x, v.y), h1 = packbf(v.z, v.w);
    uint32_t l0 = packres(h0, v.x, v.y), l1 = packres(h1, v.z, v.w);
    ((uint2*)hi)[i] = make_uint2(h0, h1);
    ((uint2*)lo)[i] = make_uint2(l0, l1);
}

// ---------------------------------------------------------------------------
// mma.sync bf16x3 GEMM:  C[M,N] = A[M,K] * B[N,K]^T
// 128x128x32 CTA tile, 128 threads = 4 warps, each warp owns 64x64.
// Double-buffered cp.async; 80B smem row stride (conflict-free ldmatrix).
// WB=1: write bf16 hi/lo outputs; WB=0: write fp32.
// ---------------------------------------------------------------------------
#define BM 128
#define BN 128
#define BKc 32
#define TILE_BYT (128 * 80)           // 80B row stride
#define STAGE_BYT (4 * TILE_BYT)
#define GEMM_SMEM (2 * STAGE_BYT)     // 81920 B

__device__ __forceinline__ void load_stage(
    uint32_t sb, int s,
    const __nv_bfloat16* __restrict__ Ah, const __nv_bfloat16* __restrict__ Al,
    const __nv_bfloat16* __restrict__ Bh, const __nv_bfloat16* __restrict__ Bl,
    int bm, int bn, int k0, int K, int tid)
{
    const __nv_bfloat16* srcs[4] = {
        Ah + (size_t)bm * K, Al + (size_t)bm * K,
        Bh + (size_t)bn * K, Bl + (size_t)bn * K };
    uint32_t base = sb + s * STAGE_BYT;
    #pragma unroll
    for (int t = 0; t < 4; ++t) {
        const __nv_bfloat16* src = srcs[t];
        uint32_t tb = base + t * TILE_BYT;
        #pragma unroll
        for (int j = 0; j < 4; ++j) {
            int idx = tid + j * 128;            // 0..511
            int row = idx >> 2, ch = idx & 3;
            CP_ASYNC16(tb + row * 80 + ch * 16,
                       src + (size_t)row * K + k0 + ch * 8);
        }
    }
}

template<int WB>
__global__ __launch_bounds__(128) void gemm_mma_bf16x3(
    const __nv_bfloat16* __restrict__ Ah, const __nv_bfloat16* __restrict__ Al,
    const __nv_bfloat16* __restrict__ Bh, const __nv_bfloat16* __restrict__ Bl,
    float* __restrict__ C, __nv_bfloat16* __restrict__ Ch,
    __nv_bfloat16* __restrict__ Cl, int K, int N)
{
    extern __shared__ char smem[];
    const uint32_t sb = smem_u32(smem);
    const int tid = threadIdx.x, wid = tid >> 5, lane = tid & 31;
    const int bm = blockIdx.y * BM, bn = blockIdx.x * BN;
    const int wm = (wid >> 1) * 64;   // warp row offset (0 or 64)
    const int wn = (wid & 1) * 64;    // warp col offset (0 or 64)

    float acc[4][8][4];
    #pragma unroll
    for (int i = 0; i < 4; ++i)
        #pragma unroll
        for (int j = 0; j < 8; ++j)
            #pragma unroll
            for (int q = 0; q < 4; ++q) acc[i][j][q] = 0.f;

    const uint32_t lrow = (lane & 15);
    const uint32_t lcol = (lane >> 4) * 16;

    const int NKB = K / BKc;
    load_stage(sb, 0, Ah, Al, Bh, Bl, bm, bn, 0, K, tid);
    CP_COMMIT();

    for (int kb = 0; kb < NKB; ++kb) {
        const int s = kb & 1;
        if (kb + 1 < NKB) {
            load_stage(sb, s ^ 1, Ah, Al, Bh, Bl, bm, bn, (kb + 1) * BKc, K, tid);
            CP_COMMIT();
            CP_WAIT(1);
        } else {
            CP_WAIT(0);
        }
        __syncthreads();

        const uint32_t stb = sb + s * STAGE_BYT;
        #pragma unroll
        for (int ks = 0; ks < 2; ++ks) {
            const uint32_t koff = ks * 32 + lcol;
            uint32_t ah[4][4], al[4][4], bh[4][4], bl[4][4];
            #pragma unroll
            for (int rt = 0; rt < 4; ++rt) {
                uint32_t ro = (wm + rt * 16 + lrow) * 80 + koff;
                LDSM_X4(ah[rt][0], ah[rt][1], ah[rt][2], ah[rt][3], stb + ro);
                LDSM_X4(al[rt][0], al[rt][1], al[rt][2], al[rt][3], stb + TILE_BYT + ro);
            }
            #pragma unroll
            for (int g = 0; g < 4; ++g) {
                uint32_t ro = (wn + g * 16 + lrow) * 80 + koff;
                LDSM_X4(bh[g][0], bh[g][1], bh[g][2], bh[g][3], stb + 2 * TILE_BYT + ro);
                LDSM_X4(bl[g][0], bl[g][1], bl[g][2], bl[g][3], stb + 3 * TILE_BYT + ro);
            }
            #pragma unroll
            for (int rt = 0; rt < 4; ++rt)
                #pragma unroll
                for (int g = 0; g < 4; ++g)
                    #pragma unroll
                    for (int sub = 0; sub < 2; ++sub) {
                        int ct = g * 2 + sub;
                        uint32_t bfh[2] = { bh[g][sub], bh[g][sub + 2] };
                        uint32_t bfl[2] = { bl[g][sub], bl[g][sub + 2] };
                        MMA16816(acc[rt][ct], ah[rt], bfh);
                        MMA16816(acc[rt][ct], ah[rt], bfl);
                        MMA16816(acc[rt][ct], al[rt], bfh);
                    }
        }
        __syncthreads();
    }

    const int r0 = bm + wm + (lane >> 2);
    const int c0 = bn + wn + (lane & 3) * 2;
    #pragma unroll
    for (int rt = 0; rt < 4; ++rt)
        #pragma unroll
        for (int ct = 0; ct < 8; ++ct) {
            size_t i0 = (size_t)(r0 + rt * 16) * N + c0 + ct * 8;
            size_t i1 = i0 + (size_t)8 * N;
            if (WB) {
                uint32_t p0 = packbf(acc[rt][ct][0], acc[rt][ct][1]);
                uint32_t p1 = packbf(acc[rt][ct][2], acc[rt][ct][3]);
                *(uint32_t*)&Ch[i0] = p0;
                *(uint32_t*)&Ch[i1] = p1;
                *(uint32_t*)&Cl[i0] = packres(p0, acc[rt][ct][0], acc[rt][ct][1]);
                *(uint32_t*)&Cl[i1] = packres(p1, acc[rt][ct][2], acc[rt][ct][3]);
            } else {
                *(float2*)&C[i0] = make_float2(acc[rt][ct][0], acc[rt][ct][1]);
                *(float2*)&C[i1] = make_float2(acc[rt][ct][2], acc[rt][ct][3]);
            }
        }
}

// ---------------------------------------------------------------------------
// Flash attention with mma.sync bf16x3. CTA: 128 q-rows x 64 kv tile, 8 warps.
// ---------------------------------------------------------------------------
#define BQa 128
#define BKVa 64
#define TST 144
#define SQH 0
#define SQL (128 * TST)
#define KVB (2 * 128 * TST)
#define KVSTG (4 * 64 * TST)
#define ATTN_SMEM (KVB + 2 * KVSTG)   // 110592 B

__global__ __launch_bounds__(256) void attn_mma(
    const __nv_bfloat16* __restrict__ qkvh, const __nv_bfloat16* __restrict__ qkvl,
    __nv_bfloat16* __restrict__ oh, __nv_bfloat16* __restrict__ ol)
{
    extern __shared__ char smem[];
    const uint32_t sb = smem_u32(smem);
    const int tid = threadIdx.x, wid = tid >> 5, lane = tid & 31;
    const int qi = (int)gridDim.x - 1 - (int)blockIdx.x;   // heavy tiles first
    const int h = blockIdx.y, b = blockIdx.z;
    const int qbase = qi * BQa;
    const int wq = wid * 16;
    const uint32_t lrow = lane & 15, lcol = (lane >> 4) * 16;
    const size_t ld = 3 * Dv;

    // Load Q tile (hi, lo)
    {
        const size_t base = ((size_t)b * Sv + qbase) * ld + (size_t)h * HDv;
        #pragma unroll
        for (int i = 0; i < 8; ++i) {
            int idx = tid + i * 256;            // 2 tiles * 128 rows * 8 chunks
            int t = idx >> 10, rr = (idx >> 3) & 127, ch = idx & 7;
            const __nv_bfloat16* src = (t ? qkvl : qkvh) + base + (size_t)rr * ld + ch * 8;
            CP_ASYNC16(sb + (t ? SQL : SQH) + rr * TST + ch * 16, src);
        }
    }

    const int ntiles = 2 * (qi + 1);
    // prologue: KV tile 0 -> stage 0
    {
        const size_t kbase = ((size_t)b * Sv) * ld + Dv + (size_t)h * HDv;
        #pragma unroll
        for (int i = 0; i < 8; ++i) {
            int idx = tid + i * 256;            // 4 tiles * 64 rows * 8 chunks
            int t = idx >> 9, rr = (idx >> 3) & 63, ch = idx & 7;
            size_t gb = kbase + ((t < 2) ? 0 : Dv);
            const __nv_bfloat16* src = ((t & 1) ? qkvl : qkvh) + gb + (size_t)rr * ld + ch * 8;
            CP_ASYNC16(sb + KVB + t * (64 * TST) + rr * TST + ch * 16, src);
        }
    }
    CP_COMMIT();

    float s[8][4], o[8][4];
    #pragma unroll
    for (int t = 0; t < 8; ++t)
        #pragma unroll
        for (int e = 0; e < 4; ++e) o[t][e] = 0.f;
    float m0 = -1e30f, m1 = -1e30f, l0 = 0.f, l1 = 0.f;

    for (int j = 0; j < ntiles; ++j) {
        const int stg = j & 1;
        if (j + 1 < ntiles) {
            const size_t kbase = ((size_t)b * Sv + (j + 1) * BKVa) * ld + Dv + (size_t)h * HDv;
            uint32_t s0 = sb + KVB + (stg ^ 1) * KVSTG;
            #pragma unroll
            for (int i = 0; i < 8; ++i) {
                int idx = tid + i * 256;
                int t = idx >> 9, rr = (idx >> 3) & 63, ch = idx & 7;
                size_t gb = kbase + ((t < 2) ? 0 : Dv);
                const __nv_bfloat16* src = ((t & 1) ? qkvl : qkvh) + gb + (size_t)rr * ld + ch * 8;
                CP_ASYNC16(s0 + t * (64 * TST) + rr * TST + ch * 16, src);
            }
            CP_COMMIT();
            CP_WAIT(1);
        } else {
            CP_WAIT(0);
        }
        __syncthreads();

        const uint32_t kh_b = sb + KVB + stg * KVSTG;
        const uint32_t kl_b = kh_b + 64 * TST;
        const uint32_t vh_b = kh_b + 2 * 64 * TST;
        const uint32_t vl_b = kh_b + 3 * 64 * TST;

        // S = Q K^T (bf16x3)
        #pragma unroll
        for (int t = 0; t < 8; ++t)
            #pragma unroll
            for (int e = 0; e < 4; ++e) s[t][e] = 0.f;
        #pragma unroll
        for (int dc = 0; dc < 4; ++dc) {
            uint32_t qoff = (wq + lrow) * TST + dc * 32 + lcol;
            uint32_t qh[4], ql[4];
            LDSM_X4(qh[0], qh[1], qh[2], qh[3], sb + SQH + qoff);
            LDSM_X4(ql[0], ql[1], ql[2], ql[3], sb + SQL + qoff);
            #pragma unroll
            for (int ng = 0; ng < 4; ++ng) {
                uint32_t koff = (ng * 16 + lrow) * TST + dc * 32 + lcol;
                uint32_t kh[4], kl[4];
                LDSM_X4(kh[0], kh[1], kh[2], kh[3], kh_b + koff);
                LDSM_X4(kl[0], kl[1], kl[2], kl[3], kl_b + koff);
                uint32_t b0h[2] = { kh[0], kh[2] }, b1h[2] = { kh[1], kh[3] };
                uint32_t b0l[2] = { kl[0], kl[2] }, b1l[2] = { kl[1], kl[3] };
                MMA16816(s[2 * ng],     qh, b0h);
                MMA16816(s[2 * ng],     qh, b0l);
                MMA16816(s[2 * ng],     ql, b0h);
                MMA16816(s[2 * ng + 1], qh, b1h);
                MMA16816(s[2 * ng + 1], qh, b1l);
                MMA16816(s[2 * ng + 1], ql, b1h);
            }
        }

        // scale + causal mask
        const int row0 = qbase + wq + (lane >> 2);
        if (j * BKVa + BKVa - 1 > qbase + wq) {
            #pragma unroll
            for (int t = 0; t < 8; ++t) {
                int colb = j * BKVa + 8 * t + (lane & 3) * 2;
                #pragma unroll
                for (int e = 0; e < 4; ++e) {
                    int col = colb + (e & 1);
                    int row = (e < 2) ? row0 : row0 + 8;
                    s[t][e] = (col > row) ? -1e30f : s[t][e] * 0.125f;
                }
            }
        } else {
            #pragma unroll
            for (int t = 0; t < 8; ++t)
                #pragma unroll
                for (int e = 0; e < 4; ++e) s[t][e] *= 0.125f;
        }

        // online softmax (rows row0, row0+8)
        float mx0 = -1e30f, mx1 = -1e30f;
        #pragma unroll
        for (int t = 0; t < 8; ++t) {
            mx0 = fmaxf(mx0, fmaxf(s[t][0], s[t][1]));
            mx1 = fmaxf(mx1, fmaxf(s[t][2], s[t][3]));
        }
        mx0 = fmaxf(mx0, __shfl_xor_sync(0xffffffffu, mx0, 1));
        mx0 = fmaxf(mx0, __shfl_xor_sync(0xffffffffu, mx0, 2));
        mx1 = fmaxf(mx1, __shfl_xor_sync(0xffffffffu, mx1, 1));
        mx1 = fmaxf(mx1, __shfl_xor_sync(0xffffffffu, mx1, 2));
        float mn0 = fmaxf(m0, mx0), mn1 = fmaxf(m1, mx1);
        float a0 = __expf(m0 - mn0), a1 = __expf(m1 - mn1);
        m0 = mn0; m1 = mn1;
        float rs0 = 0.f, rs1 = 0.f;
        #pragma unroll
        for (int t = 0; t < 8; ++t) {
            s[t][0] = __expf(s[t][0] - mn0);
            s[t][1] = __expf(s[t][1] - mn0);
            s[t][2] = __expf(s[t][2] - mn1);
            s[t][3] = __expf(s[t][3] - mn1);
            rs0 += s[t][0] + s[t][1];
            rs1 += s[t][2] + s[t][3];
            o[t][0] *= a0; o[t][1] *= a0; o[t][2] *= a1; o[t][3] *= a1;
        }
        rs0 += __shfl_xor_sync(0xffffffffu, rs0, 1);
        rs0 += __shfl_xor_sync(0xffffffffu, rs0, 2);
        rs1 += __shfl_xor_sync(0xffffffffu, rs1, 1);
        rs1 += __shfl_xor_sync(0xffffffffu, rs1, 2);
        l0 = l0 * a0 + rs0;
        l1 = l1 * a1 + rs1;

        // O += P V (P in registers via acc->A layout identity; bf16x3)
        #pragma unroll
        for (int kc = 0; kc < 4; ++kc) {
            uint32_t pah[4], pal[4];
            pah[0] = packbf(s[2 * kc][0], s[2 * kc][1]);
            pah[1] = packbf(s[2 * kc][2], s[2 * kc][3]);
            pah[2] = packbf(s[2 * kc + 1][0], s[2 * kc + 1][1]);
            pah[3] = packbf(s[2 * kc + 1][2], s[2 * kc + 1][3]);
            pal[0] = packres(pah[0], s[2 * kc][0], s[2 * kc][1]);
            pal[1] = packres(pah[1], s[2 * kc][2], s[2 * kc][3]);
            pal[2] = packres(pah[2], s[2 * kc + 1][0], s[2 * kc + 1][1]);
            pal[3] = packres(pah[3], s[2 * kc + 1][2], s[2 * kc + 1][3]);
            #pragma unroll
            for (int ng = 0; ng < 4; ++ng) {
                uint32_t voff = (kc * 16 + lrow) * TST + ng * 32 + lcol;
                uint32_t vh[4], vl[4];
                LDSM_X4_T(vh[0], vh[1], vh[2], vh[3], vh_b + voff);
                LDSM_X4_T(vl[0], vl[1], vl[2], vl[3], vl_b + voff);
                uint32_t bv0h[2] = { vh[0], vh[1] }, bv1h[2] = { vh[2], vh[3] };
                uint32_t bv0l[2] = { vl[0], vl[1] }, bv1l[2] = { vl[2], vl[3] };
                MMA16816(o[2 * ng],     pah, bv0h);
                MMA16816(o[2 * ng],     pah, bv0l);
                MMA16816(o[2 * ng],     pal, bv0h);
                MMA16816(o[2 * ng + 1], pah, bv1h);
                MMA16816(o[2 * ng + 1], pah, bv1l);
                MMA16816(o[2 * ng + 1], pal, bv1h);
            }
        }
        __syncthreads();
    }

    // epilogue: O/l -> bf16 hi/lo at [b*S + q][h*64 + n]
    const float i0 = 1.f / l0, i1 = 1.f / l1;
    const size_t r0 = (size_t)b * Sv + qbase + wq + (lane >> 2);
    const int cb = h * HDv + (lane & 3) * 2;
    #pragma unroll
    for (int t = 0; t < 8; ++t) {
        size_t ia = r0 * Dv + cb + 8 * t;
        size_t ib = ia + (size_t)8 * Dv;
        float f0 = o[t][0] * i0, f1 = o[t][1] * i0;
        float f2 = o[t][2] * i1, f3 = o[t][3] * i1;
        uint32_t p0 = packbf(f0, f1), p1 = packbf(f2, f3);
        *(uint32_t*)&oh[ia] = p0;
        *(uint32_t*)&oh[ib] = p1;
        *(uint32_t*)&ol[ia] = packres(p0, f0, f1);
        *(uint32_t*)&ol[ib] = packres(p1, f2, f3);
    }
}

// ---------------------------------------------------------------------------
extern "C" void kernel_launch(void* const* d_in, const int* in_sizes, int n_in,
                              void* d_out, int out_size)
{
    (void)in_sizes; (void)n_in; (void)out_size;
    const float* x     = (const float*)d_in[0];
    const float* w_qkv = (const float*)d_in[1];
    const float* w_out = (const float*)d_in[2];
    float* out = (float*)d_out;

    __nv_bfloat16 *xh, *xl, *wqh, *wql, *qkvh, *qkvl, *oh, *ol, *woh, *wol;
    cudaGetSymbolAddress((void**)&xh, g_xh);     cudaGetSymbolAddress((void**)&xl, g_xl);
    cudaGetSymbolAddress((void**)&wqh, g_wqh);   cudaGetSymbolAddress((void**)&wql, g_wql);
    cudaGetSymbolAddress((void**)&qkvh, g_qkvh); cudaGetSymbolAddress((void**)&qkvl, g_qkvl);
    cudaGetSymbolAddress((void**)&oh, g_oh);     cudaGetSymbolAddress((void**)&ol, g_ol);
    cudaGetSymbolAddress((void**)&woh, g_woh);   cudaGetSymbolAddress((void**)&wol, g_wol);

    cudaFuncSetAttribute(attn_mma,
                         cudaFuncAttributeMaxDynamicSharedMemorySize, ATTN_SMEM);
    cudaFuncSetAttribute(gemm_mma_bf16x3<0>,
                         cudaFuncAttributeMaxDynamicSharedMemorySize, GEMM_SMEM);
    cudaFuncSetAttribute(gemm_mma_bf16x3<1>,
                         cudaFuncAttributeMaxDynamicSharedMemorySize, GEMM_SMEM);

    // Split inputs into bf16 hi/lo
    {
        int n4 = (Mv * Dv) / 4;
        split_bf16<<<(n4 + 255) / 256, 256>>>(x, xh, xl, n4);
        n4 = (3 * Dv * Dv) / 4;
        split_bf16<<<(n4 + 255) / 256, 256>>>(w_qkv, wqh, wql, n4);
        n4 = (Dv * Dv) / 4;
        split_bf16<<<(n4 + 255) / 256, 256>>>(w_out, woh, wol, n4);
    }

    // 1) QKV projection -> bf16 hi/lo qkv
    {
        dim3 g(3 * Dv / BN, Mv / BM);
        gemm_mma_bf16x3<1><<<g, 128, GEMM_SMEM>>>(
            xh, xl, wqh, wql, nullptr, qkvh, qkvl, Dv, 3 * Dv);
    }

    // 2) Causal flash attention (mma bf16x3) -> bf16 hi/lo O
    {
        dim3 g(Sv / BQa, Hv, Bv);
        attn_mma<<<g, 256, ATTN_SMEM>>>(qkvh, qkvl, oh, ol);
    }

    // 3) Output projection -> fp32 out
    {
        dim3 g(Dv / BN, Mv / BM);
        gemm_mma_bf16x3<0><<<g, 128, GEMM_SMEM>>>(
            oh, ol, woh, wol, out, nullptr, nullptr, Dv, Dv);
    }
}

// round 6
// speedup vs baseline: 1.0267x; 1.0267x over previous
#include <cuda_runtime.h>
#include <cuda_bf16.h>
#include <math.h>
#include <stdint.h>

// Problem constants
#define Bv 2
#define Sv 2048
#define Dv 1024
#define Hv 16
#define HDv 64
#define Mv (Bv*Sv)   // 4096 rows

// ---------------------------------------------------------------------------
// Scratch (device globals: no allocation allowed)
// ---------------------------------------------------------------------------
__device__ __align__(16) __nv_bfloat16 g_xh[(size_t)Mv * Dv];
__device__ __align__(16) __nv_bfloat16 g_xl[(size_t)Mv * Dv];
__device__ __align__(16) __nv_bfloat16 g_wqh[(size_t)3 * Dv * Dv];
__device__ __align__(16) __nv_bfloat16 g_wql[(size_t)3 * Dv * Dv];
__device__ __align__(16) __nv_bfloat16 g_qkvh[(size_t)Mv * 3 * Dv];
__device__ __align__(16) __nv_bfloat16 g_qkvl[(size_t)Mv * 3 * Dv];
__device__ __align__(16) __nv_bfloat16 g_oh[(size_t)Mv * Dv];
__device__ __align__(16) __nv_bfloat16 g_ol[(size_t)Mv * Dv];
__device__ __align__(16) __nv_bfloat16 g_woh[(size_t)Dv * Dv];
__device__ __align__(16) __nv_bfloat16 g_wol[(size_t)Dv * Dv];

// ---------------------------------------------------------------------------
// PTX helpers
// ---------------------------------------------------------------------------
__device__ __forceinline__ uint32_t smem_u32(const void* p) {
    uint32_t a;
    asm("{ .reg .u64 t; cvta.to.shared.u64 t, %1; cvt.u32.u64 %0, t; }" : "=r"(a) : "l"(p));
    return a;
}
#define CP_ASYNC16(sm, g) \
    asm volatile("cp.async.cg.shared.global [%0], [%1], 16;" :: "r"(sm), "l"(g) : "memory")
#define CP_COMMIT() asm volatile("cp.async.commit_group;" ::: "memory")
#define CP_WAIT(n)  asm volatile("cp.async.wait_group %0;" :: "n"(n) : "memory")

#define LDSM_X4(r0, r1, r2, r3, addr) \
    asm volatile("ldmatrix.sync.aligned.m8n8.x4.shared.b16 {%0,%1,%2,%3}, [%4];" \
        : "=r"(r0), "=r"(r1), "=r"(r2), "=r"(r3) : "r"(addr))
#define LDSM_X4_T(r0, r1, r2, r3, addr) \
    asm volatile("ldmatrix.sync.aligned.m8n8.x4.trans.shared.b16 {%0,%1,%2,%3}, [%4];" \
        : "=r"(r0), "=r"(r1), "=r"(r2), "=r"(r3) : "r"(addr))

#define MMA16816(d, a, b) \
    asm volatile("mma.sync.aligned.m16n8k16.row.col.f32.bf16.bf16.f32 " \
        "{%0,%1,%2,%3}, {%4,%5,%6,%7}, {%8,%9}, {%0,%1,%2,%3};" \
        : "+f"((d)[0]), "+f"((d)[1]), "+f"((d)[2]), "+f"((d)[3]) \
        : "r"((a)[0]), "r"((a)[1]), "r"((a)[2]), "r"((a)[3]), "r"((b)[0]), "r"((b)[1]))

// pack(lo, hi) -> bf16x2 register (hi in upper 16 bits)
__device__ __forceinline__ uint32_t packbf(float lo, float hi) {
    uint32_t r;
    asm("cvt.rn.bf16x2.f32 %0, %1, %2;" : "=r"(r) : "f"(hi), "f"(lo));
    return r;
}
// residual of a prior packbf
__device__ __forceinline__ uint32_t packres(uint32_t h, float lo, float hi) {
    float lof = __uint_as_float(h << 16);
    float hif = __uint_as_float(h & 0xFFFF0000u);
    return packbf(lo - lof, hi - hif);
}

// ---------------------------------------------------------------------------
// fp32 -> (bf16 hi, bf16 lo) split kernel
// ---------------------------------------------------------------------------
__global__ __launch_bounds__(256) void split_bf16(
    const float* __restrict__ in, __nv_bfloat16* __restrict__ hi,
    __nv_bfloat16* __restrict__ lo, int n4)
{
    int i = blockIdx.x * blockDim.x + threadIdx.x;
    if (i >= n4) return;
    float4 v = ((const float4*)in)[i];
    uint32_t h0 = packbf(v.x, v.y), h1 = packbf(v.z, v.w);
    uint32_t l0 = packres(h0, v.x, v.y), l1 = packres(h1, v.z, v.w);
    ((uint2*)hi)[i] = make_uint2(h0, h1);
    ((uint2*)lo)[i] = make_uint2(l0, l1);
}

// ---------------------------------------------------------------------------
// Persistent mma.sync bf16x3 GEMM:  C[M,N] = A[M,K] * B[N,K]^T
// 128x128x32 CTA tile, 128 threads = 4 warps (64x64 each).
// grid = 296 persistent CTAs looping over tiles (no wave quantization).
// ---------------------------------------------------------------------------
#define BM 128
#define BN 128
#define BKc 32
#define TILE_BYT (128 * 80)           // 80B row stride
#define STAGE_BYT (4 * TILE_BYT)
#define GEMM_SMEM (2 * STAGE_BYT)     // 81920 B
#define GEMM_GRID 296

__device__ __forceinline__ void load_stage(
    uint32_t sb, int s,
    const __nv_bfloat16* __restrict__ Ah, const __nv_bfloat16* __restrict__ Al,
    const __nv_bfloat16* __restrict__ Bh, const __nv_bfloat16* __restrict__ Bl,
    int bm, int bn, int k0, int K, int tid)
{
    const __nv_bfloat16* srcs[4] = {
        Ah + (size_t)bm * K, Al + (size_t)bm * K,
        Bh + (size_t)bn * K, Bl + (size_t)bn * K };
    uint32_t base = sb + s * STAGE_BYT;
    #pragma unroll
    for (int t = 0; t < 4; ++t) {
        const __nv_bfloat16* src = srcs[t];
        uint32_t tb = base + t * TILE_BYT;
        #pragma unroll
        for (int j = 0; j < 4; ++j) {
            int idx = tid + j * 128;            // 0..511
            int row = idx >> 2, ch = idx & 3;
            CP_ASYNC16(tb + row * 80 + ch * 16,
                       src + (size_t)row * K + k0 + ch * 8);
        }
    }
}

template<int WB>
__global__ __launch_bounds__(128) void gemm_mma_bf16x3(
    const __nv_bfloat16* __restrict__ Ah, const __nv_bfloat16* __restrict__ Al,
    const __nv_bfloat16* __restrict__ Bh, const __nv_bfloat16* __restrict__ Bl,
    float* __restrict__ C, __nv_bfloat16* __restrict__ Ch,
    __nv_bfloat16* __restrict__ Cl, int M, int K, int N)
{
    extern __shared__ char smem[];
    const uint32_t sb = smem_u32(smem);
    const int tid = threadIdx.x, wid = tid >> 5, lane = tid & 31;
    const int wm = (wid >> 1) * 64;
    const int wn = (wid & 1) * 64;
    const uint32_t lrow = (lane & 15);
    const uint32_t lcol = (lane >> 4) * 16;
    const int ntn = N / BN;
    const int ntot = (M / BM) * ntn;
    const int NKB = K / BKc;

    for (int tix = blockIdx.x; tix < ntot; tix += (int)gridDim.x) {
        const int bm = (tix / ntn) * BM, bn = (tix % ntn) * BN;

        float acc[4][8][4];
        #pragma unroll
        for (int i = 0; i < 4; ++i)
            #pragma unroll
            for (int j = 0; j < 8; ++j)
                #pragma unroll
                for (int q = 0; q < 4; ++q) acc[i][j][q] = 0.f;

        load_stage(sb, 0, Ah, Al, Bh, Bl, bm, bn, 0, K, tid);
        CP_COMMIT();

        for (int kb = 0; kb < NKB; ++kb) {
            const int s = kb & 1;
            if (kb + 1 < NKB) {
                load_stage(sb, s ^ 1, Ah, Al, Bh, Bl, bm, bn, (kb + 1) * BKc, K, tid);
                CP_COMMIT();
                CP_WAIT(1);
            } else {
                CP_WAIT(0);
            }
            __syncthreads();

            const uint32_t stb = sb + s * STAGE_BYT;
            #pragma unroll
            for (int ks = 0; ks < 2; ++ks) {
                const uint32_t koff = ks * 32 + lcol;
                uint32_t ah[4][4], al[4][4], bh[4][4], bl[4][4];
                #pragma unroll
                for (int rt = 0; rt < 4; ++rt) {
                    uint32_t ro = (wm + rt * 16 + lrow) * 80 + koff;
                    LDSM_X4(ah[rt][0], ah[rt][1], ah[rt][2], ah[rt][3], stb + ro);
                    LDSM_X4(al[rt][0], al[rt][1], al[rt][2], al[rt][3], stb + TILE_BYT + ro);
                }
                #pragma unroll
                for (int g = 0; g < 4; ++g) {
                    uint32_t ro = (wn + g * 16 + lrow) * 80 + koff;
                    LDSM_X4(bh[g][0], bh[g][1], bh[g][2], bh[g][3], stb + 2 * TILE_BYT + ro);
                    LDSM_X4(bl[g][0], bl[g][1], bl[g][2], bl[g][3], stb + 3 * TILE_BYT + ro);
                }
                #pragma unroll
                for (int rt = 0; rt < 4; ++rt)
                    #pragma unroll
                    for (int g = 0; g < 4; ++g)
                        #pragma unroll
                        for (int sub = 0; sub < 2; ++sub) {
                            int ct = g * 2 + sub;
                            uint32_t bfh[2] = { bh[g][sub], bh[g][sub + 2] };
                            uint32_t bfl[2] = { bl[g][sub], bl[g][sub + 2] };
                            MMA16816(acc[rt][ct], ah[rt], bfh);
                            MMA16816(acc[rt][ct], ah[rt], bfl);
                            MMA16816(acc[rt][ct], al[rt], bfh);
                        }
            }
            __syncthreads();
        }

        const int r0 = bm + wm + (lane >> 2);
        const int c0 = bn + wn + (lane & 3) * 2;
        #pragma unroll
        for (int rt = 0; rt < 4; ++rt)
            #pragma unroll
            for (int ct = 0; ct < 8; ++ct) {
                size_t i0 = (size_t)(r0 + rt * 16) * N + c0 + ct * 8;
                size_t i1 = i0 + (size_t)8 * N;
                if (WB) {
                    uint32_t p0 = packbf(acc[rt][ct][0], acc[rt][ct][1]);
                    uint32_t p1 = packbf(acc[rt][ct][2], acc[rt][ct][3]);
                    *(uint32_t*)&Ch[i0] = p0;
                    *(uint32_t*)&Ch[i1] = p1;
                    *(uint32_t*)&Cl[i0] = packres(p0, acc[rt][ct][0], acc[rt][ct][1]);
                    *(uint32_t*)&Cl[i1] = packres(p1, acc[rt][ct][2], acc[rt][ct][3]);
                } else {
                    *(float2*)&C[i0] = make_float2(acc[rt][ct][0], acc[rt][ct][1]);
                    *(float2*)&C[i1] = make_float2(acc[rt][ct][2], acc[rt][ct][3]);
                }
            }
    }
}

// ---------------------------------------------------------------------------
// Flash attention with mma.sync bf16x3. CTA: 128 q-rows x 128 kv tile, 8 warps.
// Q/K/V hi+lo in smem (144B row stride), K/V double-buffered via cp.async.
// ---------------------------------------------------------------------------
#define BQa 128
#define BKVa 128
#define TST 144
#define SQH 0
#define SQL (128 * TST)
#define KVB (2 * 128 * TST)
#define KVSTG (4 * 128 * TST)
#define ATTN_SMEM (KVB + 2 * KVSTG)   // 184320 B

__global__ __launch_bounds__(256) void attn_mma(
    const __nv_bfloat16* __restrict__ qkvh, const __nv_bfloat16* __restrict__ qkvl,
    __nv_bfloat16* __restrict__ oh, __nv_bfloat16* __restrict__ ol)
{
    extern __shared__ char smem[];
    const uint32_t sb = smem_u32(smem);
    const int tid = threadIdx.x, wid = tid >> 5, lane = tid & 31;
    const int qi = (int)gridDim.x - 1 - (int)blockIdx.x;   // heavy tiles first
    const int h = blockIdx.y, b = blockIdx.z;
    const int qbase = qi * BQa;
    const int wq = wid * 16;
    const uint32_t lrow = lane & 15, lcol = (lane >> 4) * 16;
    const size_t ld = 3 * Dv;

    // Load Q tile (hi, lo)
    {
        const size_t base = ((size_t)b * Sv + qbase) * ld + (size_t)h * HDv;
        #pragma unroll
        for (int i = 0; i < 8; ++i) {
            int idx = tid + i * 256;            // 2 tiles * 128 rows * 8 chunks
            int t = idx >> 10, rr = (idx >> 3) & 127, ch = idx & 7;
            const __nv_bfloat16* src = (t ? qkvl : qkvh) + base + (size_t)rr * ld + ch * 8;
            CP_ASYNC16(sb + (t ? SQL : SQH) + rr * TST + ch * 16, src);
        }
    }

    const int ntiles = qi + 1;
    // prologue: KV tile 0 -> stage 0
    {
        const size_t kbase = ((size_t)b * Sv) * ld + Dv + (size_t)h * HDv;
        #pragma unroll
        for (int i = 0; i < 16; ++i) {
            int idx = tid + i * 256;            // 4 tiles * 128 rows * 8 chunks
            int t = idx >> 10, rr = (idx >> 3) & 127, ch = idx & 7;
            size_t gb = kbase + ((t < 2) ? 0 : Dv);
            const __nv_bfloat16* src = ((t & 1) ? qkvl : qkvh) + gb + (size_t)rr * ld + ch * 8;
            CP_ASYNC16(sb + KVB + t * (128 * TST) + rr * TST + ch * 16, src);
        }
    }
    CP_COMMIT();

    float s[16][4], o[8][4];
    #pragma unroll
    for (int t = 0; t < 8; ++t)
        #pragma unroll
        for (int e = 0; e < 4; ++e) o[t][e] = 0.f;
    float m0 = -1e30f, m1 = -1e30f, l0 = 0.f, l1 = 0.f;

    for (int j = 0; j < ntiles; ++j) {
        const int stg = j & 1;
        if (j + 1 < ntiles) {
            const size_t kbase = ((size_t)b * Sv + (size_t)(j + 1) * BKVa) * ld + Dv + (size_t)h * HDv;
            uint32_t s0 = sb + KVB + (stg ^ 1) * KVSTG;
            #pragma unroll
            for (int i = 0; i < 16; ++i) {
                int idx = tid + i * 256;
                int t = idx >> 10, rr = (idx >> 3) & 127, ch = idx & 7;
                size_t gb = kbase + ((t < 2) ? 0 : Dv);
                const __nv_bfloat16* src = ((t & 1) ? qkvl : qkvh) + gb + (size_t)rr * ld + ch * 8;
                CP_ASYNC16(s0 + t * (128 * TST) + rr * TST + ch * 16, src);
            }
            CP_COMMIT();
            CP_WAIT(1);
        } else {
            CP_WAIT(0);
        }
        __syncthreads();

        const uint32_t kh_b = sb + KVB + stg * KVSTG;
        const uint32_t kl_b = kh_b + 128 * TST;
        const uint32_t vh_b = kh_b + 2 * 128 * TST;
        const uint32_t vl_b = kh_b + 3 * 128 * TST;

        // S = Q K^T (bf16x3), 16 n8-tiles
        #pragma unroll
        for (int t = 0; t < 16; ++t)
            #pragma unroll
            for (int e = 0; e < 4; ++e) s[t][e] = 0.f;
        #pragma unroll
        for (int dc = 0; dc < 4; ++dc) {
            uint32_t qoff = (wq + lrow) * TST + dc * 32 + lcol;
            uint32_t qh[4], ql[4];
            LDSM_X4(qh[0], qh[1], qh[2], qh[3], sb + SQH + qoff);
            LDSM_X4(ql[0], ql[1], ql[2], ql[3], sb + SQL + qoff);
            #pragma unroll
            for (int ng = 0; ng < 8; ++ng) {
                uint32_t koff = (ng * 16 + lrow) * TST + dc * 32 + lcol;
                uint32_t kh[4], kl[4];
                LDSM_X4(kh[0], kh[1], kh[2], kh[3], kh_b + koff);
                LDSM_X4(kl[0], kl[1], kl[2], kl[3], kl_b + koff);
                uint32_t b0h[2] = { kh[0], kh[2] }, b1h[2] = { kh[1], kh[3] };
                uint32_t b0l[2] = { kl[0], kl[2] }, b1l[2] = { kl[1], kl[3] };
                MMA16816(s[2 * ng],     qh, b0h);
                MMA16816(s[2 * ng],     qh, b0l);
                MMA16816(s[2 * ng],     ql, b0h);
                MMA16816(s[2 * ng + 1], qh, b1h);
                MMA16816(s[2 * ng + 1], qh, b1l);
                MMA16816(s[2 * ng + 1], ql, b1h);
            }
        }

        // scale + causal mask (diagonal tile only)
        const int row0 = qbase + wq + (lane >> 2);
        if (j == ntiles - 1) {
            #pragma unroll
            for (int t = 0; t < 16; ++t) {
                int colb = j * BKVa + 8 * t + (lane & 3) * 2;
                #pragma unroll
                for (int e = 0; e < 4; ++e) {
                    int col = colb + (e & 1);
                    int row = (e < 2) ? row0 : row0 + 8;
                    s[t][e] = (col > row) ? -1e30f : s[t][e] * 0.125f;
                }
            }
        } else {
            #pragma unroll
            for (int t = 0; t < 16; ++t)
                #pragma unroll
                for (int e = 0; e < 4; ++e) s[t][e] *= 0.125f;
        }

        // online softmax (rows row0, row0+8)
        float mx0 = -1e30f, mx1 = -1e30f;
        #pragma unroll
        for (int t = 0; t < 16; ++t) {
            mx0 = fmaxf(mx0, fmaxf(s[t][0], s[t][1]));
            mx1 = fmaxf(mx1, fmaxf(s[t][2], s[t][3]));
        }
        mx0 = fmaxf(mx0, __shfl_xor_sync(0xffffffffu, mx0, 1));
        mx0 = fmaxf(mx0, __shfl_xor_sync(0xffffffffu, mx0, 2));
        mx1 = fmaxf(mx1, __shfl_xor_sync(0xffffffffu, mx1, 1));
        mx1 = fmaxf(mx1, __shfl_xor_sync(0xffffffffu, mx1, 2));
        float mn0 = fmaxf(m0, mx0), mn1 = fmaxf(m1, mx1);
        float a0 = __expf(m0 - mn0), a1 = __expf(m1 - mn1);
        m0 = mn0; m1 = mn1;
        float rs0 = 0.f, rs1 = 0.f;
        #pragma unroll
        for (int t = 0; t < 16; ++t) {
            s[t][0] = __expf(s[t][0] - mn0);
            s[t][1] = __expf(s[t][1] - mn0);
            s[t][2] = __expf(s[t][2] - mn1);
            s[t][3] = __expf(s[t][3] - mn1);
            rs0 += s[t][0] + s[t][1];
            rs1 += s[t][2] + s[t][3];
        }
        #pragma unroll
        for (int t = 0; t < 8; ++t) {
            o[t][0] *= a0; o[t][1] *= a0; o[t][2] *= a1; o[t][3] *= a1;
        }
        rs0 += __shfl_xor_sync(0xffffffffu, rs0, 1);
        rs0 += __shfl_xor_sync(0xffffffffu, rs0, 2);
        rs1 += __shfl_xor_sync(0xffffffffu, rs1, 1);
        rs1 += __shfl_xor_sync(0xffffffffu, rs1, 2);
        l0 = l0 * a0 + rs0;
        l1 = l1 * a1 + rs1;

        // O += P V (P in registers via acc->A layout identity; bf16x3)
        #pragma unroll
        for (int kc = 0; kc < 8; ++kc) {
            uint32_t pah[4], pal[4];
            pah[0] = packbf(s[2 * kc][0], s[2 * kc][1]);
            pah[1] = packbf(s[2 * kc][2], s[2 * kc][3]);
            pah[2] = packbf(s[2 * kc + 1][0], s[2 * kc + 1][1]);
            pah[3] = packbf(s[2 * kc + 1][2], s[2 * kc + 1][3]);
            pal[0] = packres(pah[0], s[2 * kc][0], s[2 * kc][1]);
            pal[1] = packres(pah[1], s[2 * kc][2], s[2 * kc][3]);
            pal[2] = packres(pah[2], s[2 * kc + 1][0], s[2 * kc + 1][1]);
            pal[3] = packres(pah[3], s[2 * kc + 1][2], s[2 * kc + 1][3]);
            #pragma unroll
            for (int ng = 0; ng < 4; ++ng) {
                uint32_t voff = (kc * 16 + lrow) * TST + ng * 32 + lcol;
                uint32_t vh[4], vl[4];
                LDSM_X4_T(vh[0], vh[1], vh[2], vh[3], vh_b + voff);
                LDSM_X4_T(vl[0], vl[1], vl[2], vl[3], vl_b + voff);
                uint32_t bv0h[2] = { vh[0], vh[1] }, bv1h[2] = { vh[2], vh[3] };
                uint32_t bv0l[2] = { vl[0], vl[1] }, bv1l[2] = { vl[2], vl[3] };
                MMA16816(o[2 * ng],     pah, bv0h);
                MMA16816(o[2 * ng],     pah, bv0l);
                MMA16816(o[2 * ng],     pal, bv0h);
                MMA16816(o[2 * ng + 1], pah, bv1h);
                MMA16816(o[2 * ng + 1], pah, bv1l);
                MMA16816(o[2 * ng + 1], pal, bv1h);
            }
        }
        __syncthreads();
    }

    // epilogue: O/l -> bf16 hi/lo at [b*S + q][h*64 + n]
    const float i0 = 1.f / l0, i1 = 1.f / l1;
    const size_t r0 = (size_t)b * Sv + qbase + wq + (lane >> 2);
    const int cb = h * HDv + (lane & 3) * 2;
    #pragma unroll
    for (int t = 0; t < 8; ++t) {
        size_t ia = r0 * Dv + cb + 8 * t;
        size_t ib = ia + (size_t)8 * Dv;
        float f0 = o[t][0] * i0, f1 = o[t][1] * i0;
        float f2 = o[t][2] * i1, f3 = o[t][3] * i1;
        uint32_t p0 = packbf(f0, f1), p1 = packbf(f2, f3);
        *(uint32_t*)&oh[ia] = p0;
        *(uint32_t*)&oh[ib] = p1;
        *(uint32_t*)&ol[ia] = packres(p0, f0, f1);
        *(uint32_t*)&ol[ib] = packres(p1, f2, f3);
    }
}

// ---------------------------------------------------------------------------
extern "C" void kernel_launch(void* const* d_in, const int* in_sizes, int n_in,
                              void* d_out, int out_size)
{
    (void)in_sizes; (void)n_in; (void)out_size;
    const float* x     = (const float*)d_in[0];
    const float* w_qkv = (const float*)d_in[1];
    const float* w_out = (const float*)d_in[2];
    float* out = (float*)d_out;

    __nv_bfloat16 *xh, *xl, *wqh, *wql, *qkvh, *qkvl, *oh, *ol, *woh, *wol;
    cudaGetSymbolAddress((void**)&xh, g_xh);     cudaGetSymbolAddress((void**)&xl, g_xl);
    cudaGetSymbolAddress((void**)&wqh, g_wqh);   cudaGetSymbolAddress((void**)&wql, g_wql);
    cudaGetSymbolAddress((void**)&qkvh, g_qkvh); cudaGetSymbolAddress((void**)&qkvl, g_qkvl);
    cudaGetSymbolAddress((void**)&oh, g_oh);     cudaGetSymbolAddress((void**)&ol, g_ol);
    cudaGetSymbolAddress((void**)&woh, g_woh);   cudaGetSymbolAddress((void**)&wol, g_wol);

    cudaFuncSetAttribute(attn_mma,
                         cudaFuncAttributeMaxDynamicSharedMemorySize, ATTN_SMEM);
    cudaFuncSetAttribute(gemm_mma_bf16x3<0>,
                         cudaFuncAttributeMaxDynamicSharedMemorySize, GEMM_SMEM);
    cudaFuncSetAttribute(gemm_mma_bf16x3<1>,
                         cudaFuncAttributeMaxDynamicSharedMemorySize, GEMM_SMEM);

    // Split inputs into bf16 hi/lo
    {
        int n4 = (Mv * Dv) / 4;
        split_bf16<<<(n4 + 255) / 256, 256>>>(x, xh, xl, n4);
        n4 = (3 * Dv * Dv) / 4;
        split_bf16<<<(n4 + 255) / 256, 256>>>(w_qkv, wqh, wql, n4);
        n4 = (Dv * Dv) / 4;
        split_bf16<<<(n4 + 255) / 256, 256>>>(w_out, woh, wol, n4);
    }

    // 1) QKV projection -> bf16 hi/lo qkv  (persistent grid)
    gemm_mma_bf16x3<1><<<GEMM_GRID, 128, GEMM_SMEM>>>(
        xh, xl, wqh, wql, nullptr, qkvh, qkvl, Mv, Dv, 3 * Dv);

    // 2) Causal flash attention (mma bf16x3) -> bf16 hi/lo O
    {
        dim3 g(Sv / BQa, Hv, Bv);
        attn_mma<<<g, 256, ATTN_SMEM>>>(qkvh, qkvl, oh, ol);
    }

    // 3) Output projection -> fp32 out  (persistent grid)
    gemm_mma_bf16x3<0><<<GEMM_GRID, 128, GEMM_SMEM>>>(
        oh, ol, woh, wol, out, nullptr, nullptr, Mv, Dv, Dv);
}

// round 8
// speedup vs baseline: 1.0283x; 1.0016x over previous
#include <cuda_runtime.h>
#include <cuda_bf16.h>
#include <math.h>
#include <stdint.h>

// Problem constants
#define Bv 2
#define Sv 2048
#define Dv 1024
#define Hv 16
#define HDv 64
#define Mv (Bv*Sv)   // 4096 rows

// ---------------------------------------------------------------------------
// Scratch (device globals: no allocation allowed)
// ---------------------------------------------------------------------------
__device__ __align__(16) __nv_bfloat16 g_xh[(size_t)Mv * Dv];
__device__ __align__(16) __nv_bfloat16 g_xl[(size_t)Mv * Dv];
__device__ __align__(16) __nv_bfloat16 g_wqh[(size_t)3 * Dv * Dv];
__device__ __align__(16) __nv_bfloat16 g_wql[(size_t)3 * Dv * Dv];
__device__ __align__(16) __nv_bfloat16 g_qkvh[(size_t)Mv * 3 * Dv];
__device__ __align__(16) __nv_bfloat16 g_qkvl[(size_t)Mv * 3 * Dv];
__device__ __align__(16) __nv_bfloat16 g_oh[(size_t)Mv * Dv];
__device__ __align__(16) __nv_bfloat16 g_ol[(size_t)Mv * Dv];
__device__ __align__(16) __nv_bfloat16 g_woh[(size_t)Dv * Dv];
__device__ __align__(16) __nv_bfloat16 g_wol[(size_t)Dv * Dv];

// ---------------------------------------------------------------------------
// PTX helpers
// ---------------------------------------------------------------------------
__device__ __forceinline__ uint32_t smem_u32(const void* p) {
    uint32_t a;
    asm("{ .reg .u64 t; cvta.to.shared.u64 t, %1; cvt.u32.u64 %0, t; }" : "=r"(a) : "l"(p));
    return a;
}
#define CP_ASYNC16(sm, g) \
    asm volatile("cp.async.cg.shared.global [%0], [%1], 16;" :: "r"(sm), "l"(g) : "memory")
#define CP_COMMIT() asm volatile("cp.async.commit_group;" ::: "memory")
#define CP_WAIT(n)  asm volatile("cp.async.wait_group %0;" :: "n"(n) : "memory")

#define LDSM_X4(r0, r1, r2, r3, addr) \
    asm volatile("ldmatrix.sync.aligned.m8n8.x4.shared.b16 {%0,%1,%2,%3}, [%4];" \
        : "=r"(r0), "=r"(r1), "=r"(r2), "=r"(r3) : "r"(addr))
#define LDSM_X4_T(r0, r1, r2, r3, addr) \
    asm volatile("ldmatrix.sync.aligned.m8n8.x4.trans.shared.b16 {%0,%1,%2,%3}, [%4];" \
        : "=r"(r0), "=r"(r1), "=r"(r2), "=r"(r3) : "r"(addr))

#define MMA16816(d, a, b) \
    asm volatile("mma.sync.aligned.m16n8k16.row.col.f32.bf16.bf16.f32 " \
        "{%0,%1,%2,%3}, {%4,%5,%6,%7}, {%8,%9}, {%0,%1,%2,%3};" \
        : "+f"((d)[0]), "+f"((d)[1]), "+f"((d)[2]), "+f"((d)[3]) \
        : "r"((a)[0]), "r"((a)[1]), "r"((a)[2]), "r"((a)[3]), "r"((b)[0]), "r"((b)[1]))

// pack(lo, hi) -> bf16x2 register (hi in upper 16 bits)
__device__ __forceinline__ uint32_t packbf(float lo, float hi) {
    uint32_t r;
    asm("cvt.rn.bf16x2.f32 %0, %1, %2;" : "=r"(r) : "f"(hi), "f"(lo));
    return r;
}
// residual of a prior packbf
__device__ __forceinline__ uint32_t packres(uint32_t h, float lo, float hi) {
    float lof = __uint_as_float(h << 16);
    float hif = __uint_as_float(h & 0xFFFF0000u);
    return packbf(lo - lof, hi - hif);
}

// ---------------------------------------------------------------------------
// fp32 -> (bf16 hi, bf16 lo) split kernel
// ---------------------------------------------------------------------------
__global__ __launch_bounds__(256) void split_bf16(
    const float* __restrict__ in, __nv_bfloat16* __restrict__ hi,
    __nv_bfloat16* __restrict__ lo, int n4)
{
    int i = blockIdx.x * blockDim.x + threadIdx.x;
    if (i >= n4) return;
    float4 v = ((const float4*)in)[i];
    uint32_t h0 = packbf(v.x, v.y), h1 = packbf(v.z, v.w);
    uint32_t l0 = packres(h0, v.x, v.y), l1 = packres(h1, v.z, v.w);
    ((uint2*)hi)[i] = make_uint2(h0, h1);
    ((uint2*)lo)[i] = make_uint2(l0, l1);
}

// ---------------------------------------------------------------------------
// Persistent mma.sync bf16x3 GEMM:  C[M,N] = A[M,K] * B[N,K]^T
// 128x128x32 CTA tile, 128 threads = 4 warps (64x64 each).
// MMA issue is PASS-MAJOR: each accumulator's 3 updates are separated by
// 31 independent MMAs (breaks accumulator RAW chains).
// ---------------------------------------------------------------------------
#define BM 128
#define BN 128
#define BKc 32
#define TILE_BYT (128 * 80)           // 80B row stride
#define STAGE_BYT (4 * TILE_BYT)
#define GEMM_SMEM (2 * STAGE_BYT)     // 81920 B
#define GEMM_GRID 296

__device__ __forceinline__ void load_stage(
    uint32_t sb, int s,
    const __nv_bfloat16* __restrict__ Ah, const __nv_bfloat16* __restrict__ Al,
    const __nv_bfloat16* __restrict__ Bh, const __nv_bfloat16* __restrict__ Bl,
    int bm, int bn, int k0, int K, int tid)
{
    const __nv_bfloat16* srcs[4] = {
        Ah + (size_t)bm * K, Al + (size_t)bm * K,
        Bh + (size_t)bn * K, Bl + (size_t)bn * K };
    uint32_t base = sb + s * STAGE_BYT;
    #pragma unroll
    for (int t = 0; t < 4; ++t) {
        const __nv_bfloat16* src = srcs[t];
        uint32_t tb = base + t * TILE_BYT;
        #pragma unroll
        for (int j = 0; j < 4; ++j) {
            int idx = tid + j * 128;            // 0..511
            int row = idx >> 2, ch = idx & 3;
            CP_ASYNC16(tb + row * 80 + ch * 16,
                       src + (size_t)row * K + k0 + ch * 8);
        }
    }
}

template<int WB>
__global__ __launch_bounds__(128) void gemm_mma_bf16x3(
    const __nv_bfloat16* __restrict__ Ah, const __nv_bfloat16* __restrict__ Al,
    const __nv_bfloat16* __restrict__ Bh, const __nv_bfloat16* __restrict__ Bl,
    float* __restrict__ C, __nv_bfloat16* __restrict__ Ch,
    __nv_bfloat16* __restrict__ Cl, int M, int K, int N)
{
    extern __shared__ char smem[];
    const uint32_t sb = smem_u32(smem);
    const int tid = threadIdx.x, wid = tid >> 5, lane = tid & 31;
    const int wm = (wid >> 1) * 64;
    const int wn = (wid & 1) * 64;
    const uint32_t lrow = (lane & 15);
    const uint32_t lcol = (lane >> 4) * 16;
    const int ntn = N / BN;
    const int ntot = (M / BM) * ntn;
    const int NKB = K / BKc;

    for (int tix = blockIdx.x; tix < ntot; tix += (int)gridDim.x) {
        const int bm = (tix / ntn) * BM, bn = (tix % ntn) * BN;

        float acc[4][8][4];
        #pragma unroll
        for (int i = 0; i < 4; ++i)
            #pragma unroll
            for (int j = 0; j < 8; ++j)
                #pragma unroll
                for (int q = 0; q < 4; ++q) acc[i][j][q] = 0.f;

        load_stage(sb, 0, Ah, Al, Bh, Bl, bm, bn, 0, K, tid);
        CP_COMMIT();

        for (int kb = 0; kb < NKB; ++kb) {
            const int s = kb & 1;
            if (kb + 1 < NKB) {
                load_stage(sb, s ^ 1, Ah, Al, Bh, Bl, bm, bn, (kb + 1) * BKc, K, tid);
                CP_COMMIT();
                CP_WAIT(1);
            } else {
                CP_WAIT(0);
            }
            __syncthreads();

            const uint32_t stb = sb + s * STAGE_BYT;
            #pragma unroll
            for (int ks = 0; ks < 2; ++ks) {
                const uint32_t koff = ks * 32 + lcol;
                uint32_t ah[4][4], al[4][4], bh[4][4], bl[4][4];
                #pragma unroll
                for (int rt = 0; rt < 4; ++rt) {
                    uint32_t ro = (wm + rt * 16 + lrow) * 80 + koff;
                    LDSM_X4(ah[rt][0], ah[rt][1], ah[rt][2], ah[rt][3], stb + ro);
                    LDSM_X4(al[rt][0], al[rt][1], al[rt][2], al[rt][3], stb + TILE_BYT + ro);
                }
                #pragma unroll
                for (int g = 0; g < 4; ++g) {
                    uint32_t ro = (wn + g * 16 + lrow) * 80 + koff;
                    LDSM_X4(bh[g][0], bh[g][1], bh[g][2], bh[g][3], stb + 2 * TILE_BYT + ro);
                    LDSM_X4(bl[g][0], bl[g][1], bl[g][2], bl[g][3], stb + 3 * TILE_BYT + ro);
                }
                // pass 1: Ah*Bh (32 independent MMAs)
                #pragma unroll
                for (int rt = 0; rt < 4; ++rt)
                    #pragma unroll
                    for (int g = 0; g < 4; ++g)
                        #pragma unroll
                        for (int sub = 0; sub < 2; ++sub) {
                            uint32_t bf[2] = { bh[g][sub], bh[g][sub + 2] };
                            MMA16816(acc[rt][g * 2 + sub], ah[rt], bf);
                        }
                // pass 2: Ah*Bl
                #pragma unroll
                for (int rt = 0; rt < 4; ++rt)
                    #pragma unroll
                    for (int g = 0; g < 4; ++g)
                        #pragma unroll
                        for (int sub = 0; sub < 2; ++sub) {
                            uint32_t bf[2] = { bl[g][sub], bl[g][sub + 2] };
                            MMA16816(acc[rt][g * 2 + sub], ah[rt], bf);
                        }
                // pass 3: Al*Bh
                #pragma unroll
                for (int rt = 0; rt < 4; ++rt)
                    #pragma unroll
                    for (int g = 0; g < 4; ++g)
                        #pragma unroll
                        for (int sub = 0; sub < 2; ++sub) {
                            uint32_t bf[2] = { bh[g][sub], bh[g][sub + 2] };
                            MMA16816(acc[rt][g * 2 + sub], al[rt], bf);
                        }
            }
            __syncthreads();
        }

        const int r0 = bm + wm + (lane >> 2);
        const int c0 = bn + wn + (lane & 3) * 2;
        #pragma unroll
        for (int rt = 0; rt < 4; ++rt)
            #pragma unroll
            for (int ct = 0; ct < 8; ++ct) {
                size_t i0 = (size_t)(r0 + rt * 16) * N + c0 + ct * 8;
                size_t i1 = i0 + (size_t)8 * N;
                if (WB) {
                    uint32_t p0 = packbf(acc[rt][ct][0], acc[rt][ct][1]);
                    uint32_t p1 = packbf(acc[rt][ct][2], acc[rt][ct][3]);
                    *(uint32_t*)&Ch[i0] = p0;
                    *(uint32_t*)&Ch[i1] = p1;
                    *(uint32_t*)&Cl[i0] = packres(p0, acc[rt][ct][0], acc[rt][ct][1]);
                    *(uint32_t*)&Cl[i1] = packres(p1, acc[rt][ct][2], acc[rt][ct][3]);
                } else {
                    *(float2*)&C[i0] = make_float2(acc[rt][ct][0], acc[rt][ct][1]);
                    *(float2*)&C[i1] = make_float2(acc[rt][ct][2], acc[rt][ct][3]);
                }
            }
    }
}

// ---------------------------------------------------------------------------
// Flash attention with mma.sync bf16x3. CTA: 128 q-rows x 128 kv tile, 8 warps.
// MMA issue interleaves the two n8 tiles per pass to break RAW chains.
// ---------------------------------------------------------------------------
#define BQa 128
#define BKVa 128
#define TST 144
#define SQH 0
#define SQL (128 * TST)
#define KVB (2 * 128 * TST)
#define KVSTG (4 * 128 * TST)
#define ATTN_SMEM (KVB + 2 * KVSTG)   // 184320 B

__global__ __launch_bounds__(256) void attn_mma(
    const __nv_bfloat16* __restrict__ qkvh, const __nv_bfloat16* __restrict__ qkvl,
    __nv_bfloat16* __restrict__ oh, __nv_bfloat16* __restrict__ ol)
{
    extern __shared__ char smem[];
    const uint32_t sb = smem_u32(smem);
    const int tid = threadIdx.x, wid = tid >> 5, lane = tid & 31;
    const int qi = (int)gridDim.x - 1 - (int)blockIdx.x;   // heavy tiles first
    const int h = blockIdx.y, b = blockIdx.z;
    const int qbase = qi * BQa;
    const int wq = wid * 16;
    const uint32_t lrow = lane & 15, lcol = (lane >> 4) * 16;
    const size_t ld = 3 * Dv;

    // Load Q tile (hi, lo)
    {
        const size_t base = ((size_t)b * Sv + qbase) * ld + (size_t)h * HDv;
        #pragma unroll
        for (int i = 0; i < 8; ++i) {
            int idx = tid + i * 256;
            int t = idx >> 10, rr = (idx >> 3) & 127, ch = idx & 7;
            const __nv_bfloat16* src = (t ? qkvl : qkvh) + base + (size_t)rr * ld + ch * 8;
            CP_ASYNC16(sb + (t ? SQL : SQH) + rr * TST + ch * 16, src);
        }
    }

    const int ntiles = qi + 1;
    // prologue: KV tile 0 -> stage 0
    {
        const size_t kbase = ((size_t)b * Sv) * ld + Dv + (size_t)h * HDv;
        #pragma unroll
        for (int i = 0; i < 16; ++i) {
            int idx = tid + i * 256;
            int t = idx >> 10, rr = (idx >> 3) & 127, ch = idx & 7;
            size_t gb = kbase + ((t < 2) ? 0 : Dv);
            const __nv_bfloat16* src = ((t & 1) ? qkvl : qkvh) + gb + (size_t)rr * ld + ch * 8;
            CP_ASYNC16(sb + KVB + t * (128 * TST) + rr * TST + ch * 16, src);
        }
    }
    CP_COMMIT();

    float s[16][4], o[8][4];
    #pragma unroll
    for (int t = 0; t < 8; ++t)
        #pragma unroll
        for (int e = 0; e < 4; ++e) o[t][e] = 0.f;
    float m0 = -1e30f, m1 = -1e30f, l0 = 0.f, l1 = 0.f;

    for (int j = 0; j < ntiles; ++j) {
        const int stg = j & 1;
        if (j + 1 < ntiles) {
            const size_t kbase = ((size_t)b * Sv + (size_t)(j + 1) * BKVa) * ld + Dv + (size_t)h * HDv;
            uint32_t s0 = sb + KVB + (stg ^ 1) * KVSTG;
            #pragma unroll
            for (int i = 0; i < 16; ++i) {
                int idx = tid + i * 256;
                int t = idx >> 10, rr = (idx >> 3) & 127, ch = idx & 7;
                size_t gb = kbase + ((t < 2) ? 0 : Dv);
                const __nv_bfloat16* src = ((t & 1) ? qkvl : qkvh) + gb + (size_t)rr * ld + ch * 8;
                CP_ASYNC16(s0 + t * (128 * TST) + rr * TST + ch * 16, src);
            }
            CP_COMMIT();
            CP_WAIT(1);
        } else {
            CP_WAIT(0);
        }
        __syncthreads();

        const uint32_t kh_b = sb + KVB + stg * KVSTG;
        const uint32_t kl_b = kh_b + 128 * TST;
        const uint32_t vh_b = kh_b + 2 * 128 * TST;
        const uint32_t vl_b = kh_b + 3 * 128 * TST;

        // S = Q K^T (bf16x3), 16 n8-tiles, interleaved issue
        #pragma unroll
        for (int t = 0; t < 16; ++t)
            #pragma unroll
            for (int e = 0; e < 4; ++e) s[t][e] = 0.f;
        #pragma unroll
        for (int dc = 0; dc < 4; ++dc) {
            uint32_t qoff = (wq + lrow) * TST + dc * 32 + lcol;
            uint32_t qh[4], ql[4];
            LDSM_X4(qh[0], qh[1], qh[2], qh[3], sb + SQH + qoff);
            LDSM_X4(ql[0], ql[1], ql[2], ql[3], sb + SQL + qoff);
            #pragma unroll
            for (int ng = 0; ng < 8; ++ng) {
                uint32_t koff = (ng * 16 + lrow) * TST + dc * 32 + lcol;
                uint32_t kh[4], kl[4];
                LDSM_X4(kh[0], kh[1], kh[2], kh[3], kh_b + koff);
                LDSM_X4(kl[0], kl[1], kl[2], kl[3], kl_b + koff);
                uint32_t b0h[2] = { kh[0], kh[2] }, b1h[2] = { kh[1], kh[3] };
                uint32_t b0l[2] = { kl[0], kl[2] }, b1l[2] = { kl[1], kl[3] };
                MMA16816(s[2 * ng],     qh, b0h);
                MMA16816(s[2 * ng + 1], qh, b1h);
                MMA16816(s[2 * ng],     qh, b0l);
                MMA16816(s[2 * ng + 1], qh, b1l);
                MMA16816(s[2 * ng],     ql, b0h);
                MMA16816(s[2 * ng + 1], ql, b1h);
            }
        }

        // scale + causal mask (diagonal tile only)
        const int row0 = qbase + wq + (lane >> 2);
        if (j == ntiles - 1) {
            #pragma unroll
            for (int t = 0; t < 16; ++t) {
                int colb = j * BKVa + 8 * t + (lane & 3) * 2;
                #pragma unroll
                for (int e = 0; e < 4; ++e) {
                    int col = colb + (e & 1);
                    int row = (e < 2) ? row0 : row0 + 8;
                    s[t][e] = (col > row) ? -1e30f : s[t][e] * 0.125f;
                }
            }
        } else {
            #pragma unroll
            for (int t = 0; t < 16; ++t)
                #pragma unroll
                for (int e = 0; e < 4; ++e) s[t][e] *= 0.125f;
        }

        // online softmax
        float mx0 = -1e30f, mx1 = -1e30f;
        #pragma unroll
        for (int t = 0; t < 16; ++t) {
            mx0 = fmaxf(mx0, fmaxf(s[t][0], s[t][1]));
            mx1 = fmaxf(mx1, fmaxf(s[t][2], s[t][3]));
        }
        mx0 = fmaxf(mx0, __shfl_xor_sync(0xffffffffu, mx0, 1));
        mx0 = fmaxf(mx0, __shfl_xor_sync(0xffffffffu, mx0, 2));
        mx1 = fmaxf(mx1, __shfl_xor_sync(0xffffffffu, mx1, 1));
        mx1 = fmaxf(mx1, __shfl_xor_sync(0xffffffffu, mx1, 2));
        float mn0 = fmaxf(m0, mx0), mn1 = fmaxf(m1, mx1);
        float a0 = __expf(m0 - mn0), a1 = __expf(m1 - mn1);
        m0 = mn0; m1 = mn1;
        float rs0 = 0.f, rs1 = 0.f;
        #pragma unroll
        for (int t = 0; t < 16; ++t) {
            s[t][0] = __expf(s[t][0] - mn0);
            s[t][1] = __expf(s[t][1] - mn0);
            s[t][2] = __expf(s[t][2] - mn1);
            s[t][3] = __expf(s[t][3] - mn1);
            rs0 += s[t][0] + s[t][1];
            rs1 += s[t][2] + s[t][3];
        }
        #pragma unroll
        for (int t = 0; t < 8; ++t) {
            o[t][0] *= a0; o[t][1] *= a0; o[t][2] *= a1; o[t][3] *= a1;
        }
        rs0 += __shfl_xor_sync(0xffffffffu, rs0, 1);
        rs0 += __shfl_xor_sync(0xffffffffu, rs0, 2);
        rs1 += __shfl_xor_sync(0xffffffffu, rs1, 1);
        rs1 += __shfl_xor_sync(0xffffffffu, rs1, 2);
        l0 = l0 * a0 + rs0;
        l1 = l1 * a1 + rs1;

        // O += P V (bf16x3, P in registers), interleaved issue
        #pragma unroll
        for (int kc = 0; kc < 8; ++kc) {
            uint32_t pah[4], pal[4];
            pah[0] = packbf(s[2 * kc][0], s[2 * kc][1]);
            pah[1] = packbf(s[2 * kc][2], s[2 * kc][3]);
            pah[2] = packbf(s[2 * kc + 1][0], s[2 * kc + 1][1]);
            pah[3] = packbf(s[2 * kc + 1][2], s[2 * kc + 1][3]);
            pal[0] = packres(pah[0], s[2 * kc][0], s[2 * kc][1]);
            pal[1] = packres(pah[1], s[2 * kc][2], s[2 * kc][3]);
            pal[2] = packres(pah[2], s[2 * kc + 1][0], s[2 * kc + 1][1]);
            pal[3] = packres(pah[3], s[2 * kc + 1][2], s[2 * kc + 1][3]);
            #pragma unroll
            for (int ng = 0; ng < 4; ++ng) {
                uint32_t voff = (kc * 16 + lrow) * TST + ng * 32 + lcol;
                uint32_t vh[4], vl[4];
                LDSM_X4_T(vh[0], vh[1], vh[2], vh[3], vh_b + voff);
                LDSM_X4_T(vl[0], vl[1], vl[2], vl[3], vl_b + voff);
                uint32_t bv0h[2] = { vh[0], vh[1] }, bv1h[2] = { vh[2], vh[3] };
                uint32_t bv0l[2] = { vl[0], vl[1] }, bv1l[2] = { vl[2], vl[3] };
                MMA16816(o[2 * ng],     pah, bv0h);
                MMA16816(o[2 * ng + 1], pah, bv1h);
                MMA16816(o[2 * ng],     pah, bv0l);
                MMA16816(o[2 * ng + 1], pah, bv1l);
                MMA16816(o[2 * ng],     pal, bv0h);
                MMA16816(o[2 * ng + 1], pal, bv1h);
            }
        }
        __syncthreads();
    }

    // epilogue: O/l -> bf16 hi/lo at [b*S + q][h*64 + n]
    const float i0 = 1.f / l0, i1 = 1.f / l1;
    const size_t r0 = (size_t)b * Sv + qbase + wq + (lane >> 2);
    const int cb = h * HDv + (lane & 3) * 2;
    #pragma unroll
    for (int t = 0; t < 8; ++t) {
        size_t ia = r0 * Dv + cb + 8 * t;
        size_t ib = ia + (size_t)8 * Dv;
        float f0 = o[t][0] * i0, f1 = o[t][1] * i0;
        float f2 = o[t][2] * i1, f3 = o[t][3] * i1;
        uint32_t p0 = packbf(f0, f1), p1 = packbf(f2, f3);
        *(uint32_t*)&oh[ia] = p0;
        *(uint32_t*)&oh[ib] = p1;
        *(uint32_t*)&ol[ia] = packres(p0, f0, f1);
        *(uint32_t*)&ol[ib] = packres(p1, f2, f3);
    }
}

// ---------------------------------------------------------------------------
extern "C" void kernel_launch(void* const* d_in, const int* in_sizes, int n_in,
                              void* d_out, int out_size)
{
    (void)in_sizes; (void)n_in; (void)out_size;
    const float* x     = (const float*)d_in[0];
    const float* w_qkv = (const float*)d_in[1];
    const float* w_out = (const float*)d_in[2];
    float* out = (float*)d_out;

    __nv_bfloat16 *xh, *xl, *wqh, *wql, *qkvh, *qkvl, *oh, *ol, *woh, *wol;
    cudaGetSymbolAddress((void**)&xh, g_xh);     cudaGetSymbolAddress((void**)&xl, g_xl);
    cudaGetSymbolAddress((void**)&wqh, g_wqh);   cudaGetSymbolAddress((void**)&wql, g_wql);
    cudaGetSymbolAddress((void**)&qkvh, g_qkvh); cudaGetSymbolAddress((void**)&qkvl, g_qkvl);
    cudaGetSymbolAddress((void**)&oh, g_oh);     cudaGetSymbolAddress((void**)&ol, g_ol);
    cudaGetSymbolAddress((void**)&woh, g_woh);   cudaGetSymbolAddress((void**)&wol, g_wol);

    cudaFuncSetAttribute(attn_mma,
                         cudaFuncAttributeMaxDynamicSharedMemorySize, ATTN_SMEM);
    cudaFuncSetAttribute(gemm_mma_bf16x3<0>,
                         cudaFuncAttributeMaxDynamicSharedMemorySize, GEMM_SMEM);
    cudaFuncSetAttribute(gemm_mma_bf16x3<1>,
                         cudaFuncAttributeMaxDynamicSharedMemorySize, GEMM_SMEM);

    // Split inputs into bf16 hi/lo
    {
        int n4 = (Mv * Dv) / 4;
        split_bf16<<<(n4 + 255) / 256, 256>>>(x, xh, xl, n4);
        n4 = (3 * Dv * Dv) / 4;
        split_bf16<<<(n4 + 255) / 256, 256>>>(w_qkv, wqh, wql, n4);
        n4 = (Dv * Dv) / 4;
        split_bf16<<<(n4 + 255) / 256, 256>>>(w_out, woh, wol, n4);
    }

    // 1) QKV projection -> bf16 hi/lo qkv  (persistent grid)
    gemm_mma_bf16x3<1><<<GEMM_GRID, 128, GEMM_SMEM>>>(
        xh, xl, wqh, wql, nullptr, qkvh, qkvl, Mv, Dv, 3 * Dv);

    // 2) Causal flash attention (mma bf16x3) -> bf16 hi/lo O
    {
        dim3 g(Sv / BQa, Hv, Bv);
        attn_mma<<<g, 256, ATTN_SMEM>>>(qkvh, qkvl, oh, ol);
    }

    // 3) Output projection -> fp32 out  (persistent grid)
    gemm_mma_bf16x3<0><<<GEMM_GRID, 128, GEMM_SMEM>>>(
        oh, ol, woh, wol, out, nullptr, nullptr, Mv, Dv, Dv);
}

// round 9
// speedup vs baseline: 1.2485x; 1.2141x over previous
#include <cuda_runtime.h>
#include <cuda_fp16.h>
#include <math.h>
#include <stdint.h>

// Problem constants
#define Bv 2
#define Sv 2048
#define Dv 1024
#define Hv 16
#define HDv 64
#define Mv (Bv*Sv)   // 4096 rows

// ---------------------------------------------------------------------------
// Scratch (device globals: no allocation allowed)
// ---------------------------------------------------------------------------
__device__ __align__(16) __half g_xh[(size_t)Mv * Dv];
__device__ __align__(16) __half g_xl[(size_t)Mv * Dv];
__device__ __align__(16) __half g_wq[(size_t)3 * Dv * Dv];
__device__ __align__(16) __half g_qkvh[(size_t)Mv * 3 * Dv];
__device__ __align__(16) __half g_qkvl[(size_t)Mv * 3 * Dv];
__device__ __align__(16) __half g_oh[(size_t)Mv * Dv];
__device__ __align__(16) __half g_ol[(size_t)Mv * Dv];
__device__ __align__(16) __half g_wo[(size_t)Dv * Dv];

// ---------------------------------------------------------------------------
// PTX helpers
// ---------------------------------------------------------------------------
__device__ __forceinline__ uint32_t smem_u32(const void* p) {
    uint32_t a;
    asm("{ .reg .u64 t; cvta.to.shared.u64 t, %1; cvt.u32.u64 %0, t; }" : "=r"(a) : "l"(p));
    return a;
}
#define CP_ASYNC16(sm, g) \
    asm volatile("cp.async.cg.shared.global [%0], [%1], 16;" :: "r"(sm), "l"(g) : "memory")
#define CP_COMMIT() asm volatile("cp.async.commit_group;" ::: "memory")
#define CP_WAIT(n)  asm volatile("cp.async.wait_group %0;" :: "n"(n) : "memory")

#define LDSM_X4(r0, r1, r2, r3, addr) \
    asm volatile("ldmatrix.sync.aligned.m8n8.x4.shared.b16 {%0,%1,%2,%3}, [%4];" \
        : "=r"(r0), "=r"(r1), "=r"(r2), "=r"(r3) : "r"(addr))
#define LDSM_X4_T(r0, r1, r2, r3, addr) \
    asm volatile("ldmatrix.sync.aligned.m8n8.x4.trans.shared.b16 {%0,%1,%2,%3}, [%4];" \
        : "=r"(r0), "=r"(r1), "=r"(r2), "=r"(r3) : "r"(addr))

// fp16 mma, fp32 accumulate
#define MMAH(d, a, b) \
    asm volatile("mma.sync.aligned.m16n8k16.row.col.f32.f16.f16.f32 " \
        "{%0,%1,%2,%3}, {%4,%5,%6,%7}, {%8,%9}, {%0,%1,%2,%3};" \
        : "+f"((d)[0]), "+f"((d)[1]), "+f"((d)[2]), "+f"((d)[3]) \
        : "r"((a)[0]), "r"((a)[1]), "r"((a)[2]), "r"((a)[3]), "r"((b)[0]), "r"((b)[1]))

// pack(lo, hi) -> f16x2 register (lo in low 16 bits)
__device__ __forceinline__ uint32_t packh(float lo, float hi) {
    __half2 h = __floats2half2_rn(lo, hi);
    return *reinterpret_cast<uint32_t*>(&h);
}
// residual of a prior packh
__device__ __forceinline__ uint32_t packresh(uint32_t h, float lo, float hi) {
    __half2 hh = *reinterpret_cast<__half2*>(&h);
    return packh(lo - __low2float(hh), hi - __high2float(hh));
}

// ---------------------------------------------------------------------------
// fp32 -> (fp16 hi, fp16 lo residual)
// ---------------------------------------------------------------------------
__global__ __launch_bounds__(256) void split_h(
    const float* __restrict__ in, __half* __restrict__ hi,
    __half* __restrict__ lo, int n4)
{
    int i = blockIdx.x * blockDim.x + threadIdx.x;
    if (i >= n4) return;
    float4 v = ((const float4*)in)[i];
    uint32_t h0 = packh(v.x, v.y), h1 = packh(v.z, v.w);
    uint32_t l0 = packresh(h0, v.x, v.y), l1 = packresh(h1, v.z, v.w);
    ((uint2*)hi)[i] = make_uint2(h0, h1);
    ((uint2*)lo)[i] = make_uint2(l0, l1);
}

// fp32 -> fp16 (single)
__global__ __launch_bounds__(256) void cvt_h(
    const float* __restrict__ in, __half* __restrict__ out, int n4)
{
    int i = blockIdx.x * blockDim.x + threadIdx.x;
    if (i >= n4) return;
    float4 v = ((const float4*)in)[i];
    ((uint2*)out)[i] = make_uint2(packh(v.x, v.y), packh(v.z, v.w));
}

// ---------------------------------------------------------------------------
// Persistent mma.sync fp16x2 GEMM:  C[M,N] = A[M,K] * B[N,K]^T
//   pass 1: Ah*B, pass 2: Al*B   (B single fp16; error ~2^-12 from B rounding)
// 128x128x32 CTA tile, 128 threads = 4 warps (64x64 each).
// ---------------------------------------------------------------------------
#define BM 128
#define BN 128
#define BKc 32
#define TILE_BYT (128 * 80)           // 80B row stride
#define STAGE_BYT (3 * TILE_BYT)      // Ah, Al, B
#define GEMM_SMEM (2 * STAGE_BYT)     // 61440 B
#define GEMM_GRID 296

__device__ __forceinline__ void load_stage(
    uint32_t sb, int s,
    const __half* __restrict__ Ah, const __half* __restrict__ Al,
    const __half* __restrict__ B,
    int bm, int bn, int k0, int K, int tid)
{
    const __half* srcs[3] = {
        Ah + (size_t)bm * K, Al + (size_t)bm * K, B + (size_t)bn * K };
    uint32_t base = sb + s * STAGE_BYT;
    #pragma unroll
    for (int t = 0; t < 3; ++t) {
        const __half* src = srcs[t];
        uint32_t tb = base + t * TILE_BYT;
        #pragma unroll
        for (int j = 0; j < 4; ++j) {
            int idx = tid + j * 128;            // 0..511
            int row = idx >> 2, ch = idx & 3;
            CP_ASYNC16(tb + row * 80 + ch * 16,
                       src + (size_t)row * K + k0 + ch * 8);
        }
    }
}

template<int WB>
__global__ __launch_bounds__(128) void gemm_mma_h2(
    const __half* __restrict__ Ah, const __half* __restrict__ Al,
    const __half* __restrict__ B,
    float* __restrict__ C, __half* __restrict__ Ch,
    __half* __restrict__ Cl, int M, int K, int N)
{
    extern __shared__ char smem[];
    const uint32_t sb = smem_u32(smem);
    const int tid = threadIdx.x, wid = tid >> 5, lane = tid & 31;
    const int wm = (wid >> 1) * 64;
    const int wn = (wid & 1) * 64;
    const uint32_t lrow = (lane & 15);
    const uint32_t lcol = (lane >> 4) * 16;
    const int ntn = N / BN;
    const int ntot = (M / BM) * ntn;
    const int NKB = K / BKc;

    for (int tix = blockIdx.x; tix < ntot; tix += (int)gridDim.x) {
        const int bm = (tix / ntn) * BM, bn = (tix % ntn) * BN;

        float acc[4][8][4];
        #pragma unroll
        for (int i = 0; i < 4; ++i)
            #pragma unroll
            for (int j = 0; j < 8; ++j)
                #pragma unroll
                for (int q = 0; q < 4; ++q) acc[i][j][q] = 0.f;

        load_stage(sb, 0, Ah, Al, B, bm, bn, 0, K, tid);
        CP_COMMIT();

        for (int kb = 0; kb < NKB; ++kb) {
            const int s = kb & 1;
            if (kb + 1 < NKB) {
                load_stage(sb, s ^ 1, Ah, Al, B, bm, bn, (kb + 1) * BKc, K, tid);
                CP_COMMIT();
                CP_WAIT(1);
            } else {
                CP_WAIT(0);
            }
            __syncthreads();

            const uint32_t stb = sb + s * STAGE_BYT;
            #pragma unroll
            for (int ks = 0; ks < 2; ++ks) {
                const uint32_t koff = ks * 32 + lcol;
                uint32_t ah[4][4], al[4][4], bb[4][4];
                #pragma unroll
                for (int rt = 0; rt < 4; ++rt) {
                    uint32_t ro = (wm + rt * 16 + lrow) * 80 + koff;
                    LDSM_X4(ah[rt][0], ah[rt][1], ah[rt][2], ah[rt][3], stb + ro);
                    LDSM_X4(al[rt][0], al[rt][1], al[rt][2], al[rt][3], stb + TILE_BYT + ro);
                }
                #pragma unroll
                for (int g = 0; g < 4; ++g) {
                    uint32_t ro = (wn + g * 16 + lrow) * 80 + koff;
                    LDSM_X4(bb[g][0], bb[g][1], bb[g][2], bb[g][3], stb + 2 * TILE_BYT + ro);
                }
                // pass 1: Ah*B
                #pragma unroll
                for (int rt = 0; rt < 4; ++rt)
                    #pragma unroll
                    for (int g = 0; g < 4; ++g)
                        #pragma unroll
                        for (int sub = 0; sub < 2; ++sub) {
                            uint32_t bf[2] = { bb[g][sub], bb[g][sub + 2] };
                            MMAH(acc[rt][g * 2 + sub], ah[rt], bf);
                        }
                // pass 2: Al*B
                #pragma unroll
                for (int rt = 0; rt < 4; ++rt)
                    #pragma unroll
                    for (int g = 0; g < 4; ++g)
                        #pragma unroll
                        for (int sub = 0; sub < 2; ++sub) {
                            uint32_t bf[2] = { bb[g][sub], bb[g][sub + 2] };
                            MMAH(acc[rt][g * 2 + sub], al[rt], bf);
                        }
            }
            __syncthreads();
        }

        const int r0 = bm + wm + (lane >> 2);
        const int c0 = bn + wn + (lane & 3) * 2;
        #pragma unroll
        for (int rt = 0; rt < 4; ++rt)
            #pragma unroll
            for (int ct = 0; ct < 8; ++ct) {
                size_t i0 = (size_t)(r0 + rt * 16) * N + c0 + ct * 8;
                size_t i1 = i0 + (size_t)8 * N;
                if (WB) {
                    uint32_t p0 = packh(acc[rt][ct][0], acc[rt][ct][1]);
                    uint32_t p1 = packh(acc[rt][ct][2], acc[rt][ct][3]);
                    *(uint32_t*)&Ch[i0] = p0;
                    *(uint32_t*)&Ch[i1] = p1;
                    *(uint32_t*)&Cl[i0] = packresh(p0, acc[rt][ct][0], acc[rt][ct][1]);
                    *(uint32_t*)&Cl[i1] = packresh(p1, acc[rt][ct][2], acc[rt][ct][3]);
                } else {
                    *(float2*)&C[i0] = make_float2(acc[rt][ct][0], acc[rt][ct][1]);
                    *(float2*)&C[i1] = make_float2(acc[rt][ct][2], acc[rt][ct][3]);
                }
            }
    }
}

// ---------------------------------------------------------------------------
// Flash attention with mma.sync fp16x3. CTA: 128 q-rows x 128 kv tile, 8 warps.
// ---------------------------------------------------------------------------
#define BQa 128
#define BKVa 128
#define TST 144
#define SQH 0
#define SQL (128 * TST)
#define KVB (2 * 128 * TST)
#define KVSTG (4 * 128 * TST)
#define ATTN_SMEM (KVB + 2 * KVSTG)   // 184320 B

__global__ __launch_bounds__(256) void attn_mma(
    const __half* __restrict__ qkvh, const __half* __restrict__ qkvl,
    __half* __restrict__ oh, __half* __restrict__ ol)
{
    extern __shared__ char smem[];
    const uint32_t sb = smem_u32(smem);
    const int tid = threadIdx.x, wid = tid >> 5, lane = tid & 31;
    const int qi = (int)gridDim.x - 1 - (int)blockIdx.x;   // heavy tiles first
    const int h = blockIdx.y, b = blockIdx.z;
    const int qbase = qi * BQa;
    const int wq = wid * 16;
    const uint32_t lrow = lane & 15, lcol = (lane >> 4) * 16;
    const size_t ld = 3 * Dv;

    // Load Q tile (hi, lo)
    {
        const size_t base = ((size_t)b * Sv + qbase) * ld + (size_t)h * HDv;
        #pragma unroll
        for (int i = 0; i < 8; ++i) {
            int idx = tid + i * 256;
            int t = idx >> 10, rr = (idx >> 3) & 127, ch = idx & 7;
            const __half* src = (t ? qkvl : qkvh) + base + (size_t)rr * ld + ch * 8;
            CP_ASYNC16(sb + (t ? SQL : SQH) + rr * TST + ch * 16, src);
        }
    }

    const int ntiles = qi + 1;
    // prologue: KV tile 0 -> stage 0
    {
        const size_t kbase = ((size_t)b * Sv) * ld + Dv + (size_t)h * HDv;
        #pragma unroll
        for (int i = 0; i < 16; ++i) {
            int idx = tid + i * 256;
            int t = idx >> 10, rr = (idx >> 3) & 127, ch = idx & 7;
            size_t gb = kbase + ((t < 2) ? 0 : Dv);
            const __half* src = ((t & 1) ? qkvl : qkvh) + gb + (size_t)rr * ld + ch * 8;
            CP_ASYNC16(sb + KVB + t * (128 * TST) + rr * TST + ch * 16, src);
        }
    }
    CP_COMMIT();

    float s[16][4], o[8][4];
    #pragma unroll
    for (int t = 0; t < 8; ++t)
        #pragma unroll
        for (int e = 0; e < 4; ++e) o[t][e] = 0.f;
    float m0 = -1e30f, m1 = -1e30f, l0 = 0.f, l1 = 0.f;

    for (int j = 0; j < ntiles; ++j) {
        const int stg = j & 1;
        if (j + 1 < ntiles) {
            const size_t kbase = ((size_t)b * Sv + (size_t)(j + 1) * BKVa) * ld + Dv + (size_t)h * HDv;
            uint32_t s0 = sb + KVB + (stg ^ 1) * KVSTG;
            #pragma unroll
            for (int i = 0; i < 16; ++i) {
                int idx = tid + i * 256;
                int t = idx >> 10, rr = (idx >> 3) & 127, ch = idx & 7;
                size_t gb = kbase + ((t < 2) ? 0 : Dv);
                const __half* src = ((t & 1) ? qkvl : qkvh) + gb + (size_t)rr * ld + ch * 8;
                CP_ASYNC16(s0 + t * (128 * TST) + rr * TST + ch * 16, src);
            }
            CP_COMMIT();
            CP_WAIT(1);
        } else {
            CP_WAIT(0);
        }
        __syncthreads();

        const uint32_t kh_b = sb + KVB + stg * KVSTG;
        const uint32_t kl_b = kh_b + 128 * TST;
        const uint32_t vh_b = kh_b + 2 * 128 * TST;
        const uint32_t vl_b = kh_b + 3 * 128 * TST;

        // S = Q K^T (fp16x3), 16 n8-tiles, interleaved issue
        #pragma unroll
        for (int t = 0; t < 16; ++t)
            #pragma unroll
            for (int e = 0; e < 4; ++e) s[t][e] = 0.f;
        #pragma unroll
        for (int dc = 0; dc < 4; ++dc) {
            uint32_t qoff = (wq + lrow) * TST + dc * 32 + lcol;
            uint32_t qh[4], ql[4];
            LDSM_X4(qh[0], qh[1], qh[2], qh[3], sb + SQH + qoff);
            LDSM_X4(ql[0], ql[1], ql[2], ql[3], sb + SQL + qoff);
            #pragma unroll
            for (int ng = 0; ng < 8; ++ng) {
                uint32_t koff = (ng * 16 + lrow) * TST + dc * 32 + lcol;
                uint32_t kh[4], kl[4];
                LDSM_X4(kh[0], kh[1], kh[2], kh[3], kh_b + koff);
                LDSM_X4(kl[0], kl[1], kl[2], kl[3], kl_b + koff);
                uint32_t b0h[2] = { kh[0], kh[2] }, b1h[2] = { kh[1], kh[3] };
                uint32_t b0l[2] = { kl[0], kl[2] }, b1l[2] = { kl[1], kl[3] };
                MMAH(s[2 * ng],     qh, b0h);
                MMAH(s[2 * ng + 1], qh, b1h);
                MMAH(s[2 * ng],     qh, b0l);
                MMAH(s[2 * ng + 1], qh, b1l);
                MMAH(s[2 * ng],     ql, b0h);
                MMAH(s[2 * ng + 1], ql, b1h);
            }
        }

        // scale + causal mask (diagonal tile only)
        const int row0 = qbase + wq + (lane >> 2);
        if (j == ntiles - 1) {
            #pragma unroll
            for (int t = 0; t < 16; ++t) {
                int colb = j * BKVa + 8 * t + (lane & 3) * 2;
                #pragma unroll
                for (int e = 0; e < 4; ++e) {
                    int col = colb + (e & 1);
                    int row = (e < 2) ? row0 : row0 + 8;
                    s[t][e] = (col > row) ? -1e30f : s[t][e] * 0.125f;
                }
            }
        } else {
            #pragma unroll
            for (int t = 0; t < 16; ++t)
                #pragma unroll
                for (int e = 0; e < 4; ++e) s[t][e] *= 0.125f;
        }

        // online softmax
        float mx0 = -1e30f, mx1 = -1e30f;
        #pragma unroll
        for (int t = 0; t < 16; ++t) {
            mx0 = fmaxf(mx0, fmaxf(s[t][0], s[t][1]));
            mx1 = fmaxf(mx1, fmaxf(s[t][2], s[t][3]));
        }
        mx0 = fmaxf(mx0, __shfl_xor_sync(0xffffffffu, mx0, 1));
        mx0 = fmaxf(mx0, __shfl_xor_sync(0xffffffffu, mx0, 2));
        mx1 = fmaxf(mx1, __shfl_xor_sync(0xffffffffu, mx1, 1));
        mx1 = fmaxf(mx1, __shfl_xor_sync(0xffffffffu, mx1, 2));
        float mn0 = fmaxf(m0, mx0), mn1 = fmaxf(m1, mx1);
        float a0 = __expf(m0 - mn0), a1 = __expf(m1 - mn1);
        m0 = mn0; m1 = mn1;
        float rs0 = 0.f, rs1 = 0.f;
        #pragma unroll
        for (int t = 0; t < 16; ++t) {
            s[t][0] = __expf(s[t][0] - mn0);
            s[t][1] = __expf(s[t][1] - mn0);
            s[t][2] = __expf(s[t][2] - mn1);
            s[t][3] = __expf(s[t][3] - mn1);
            rs0 += s[t][0] + s[t][1];
            rs1 += s[t][2] + s[t][3];
        }
        #pragma unroll
        for (int t = 0; t < 8; ++t) {
            o[t][0] *= a0; o[t][1] *= a0; o[t][2] *= a1; o[t][3] *= a1;
        }
        rs0 += __shfl_xor_sync(0xffffffffu, rs0, 1);
        rs0 += __shfl_xor_sync(0xffffffffu, rs0, 2);
        rs1 += __shfl_xor_sync(0xffffffffu, rs1, 1);
        rs1 += __shfl_xor_sync(0xffffffffu, rs1, 2);
        l0 = l0 * a0 + rs0;
        l1 = l1 * a1 + rs1;

        // O += P V (fp16x3, P in registers), interleaved issue
        #pragma unroll
        for (int kc = 0; kc < 8; ++kc) {
            uint32_t pah[4], pal[4];
            pah[0] = packh(s[2 * kc][0], s[2 * kc][1]);
            pah[1] = packh(s[2 * kc][2], s[2 * kc][3]);
            pah[2] = packh(s[2 * kc + 1][0], s[2 * kc + 1][1]);
            pah[3] = packh(s[2 * kc + 1][2], s[2 * kc + 1][3]);
            pal[0] = packresh(pah[0], s[2 * kc][0], s[2 * kc][1]);
            pal[1] = packresh(pah[1], s[2 * kc][2], s[2 * kc][3]);
            pal[2] = packresh(pah[2], s[2 * kc + 1][0], s[2 * kc + 1][1]);
            pal[3] = packresh(pah[3], s[2 * kc + 1][2], s[2 * kc + 1][3]);
            #pragma unroll
            for (int ng = 0; ng < 4; ++ng) {
                uint32_t voff = (kc * 16 + lrow) * TST + ng * 32 + lcol;
                uint32_t vh[4], vl[4];
                LDSM_X4_T(vh[0], vh[1], vh[2], vh[3], vh_b + voff);
                LDSM_X4_T(vl[0], vl[1], vl[2], vl[3], vl_b + voff);
                uint32_t bv0h[2] = { vh[0], vh[1] }, bv1h[2] = { vh[2], vh[3] };
                uint32_t bv0l[2] = { vl[0], vl[1] }, bv1l[2] = { vl[2], vl[3] };
                MMAH(o[2 * ng],     pah, bv0h);
                MMAH(o[2 * ng + 1], pah, bv1h);
                MMAH(o[2 * ng],     pah, bv0l);
                MMAH(o[2 * ng + 1], pah, bv1l);
                MMAH(o[2 * ng],     pal, bv0h);
                MMAH(o[2 * ng + 1], pal, bv1h);
            }
        }
        __syncthreads();
    }

    // epilogue: O/l -> fp16 hi/lo at [b*S + q][h*64 + n]
    const float i0 = 1.f / l0, i1 = 1.f / l1;
    const size_t r0 = (size_t)b * Sv + qbase + wq + (lane >> 2);
    const int cb = h * HDv + (lane & 3) * 2;
    #pragma unroll
    for (int t = 0; t < 8; ++t) {
        size_t ia = r0 * Dv + cb + 8 * t;
        size_t ib = ia + (size_t)8 * Dv;
        float f0 = o[t][0] * i0, f1 = o[t][1] * i0;
        float f2 = o[t][2] * i1, f3 = o[t][3] * i1;
        uint32_t p0 = packh(f0, f1), p1 = packh(f2, f3);
        *(uint32_t*)&oh[ia] = p0;
        *(uint32_t*)&oh[ib] = p1;
        *(uint32_t*)&ol[ia] = packresh(p0, f0, f1);
        *(uint32_t*)&ol[ib] = packresh(p1, f2, f3);
    }
}

// ---------------------------------------------------------------------------
extern "C" void kernel_launch(void* const* d_in, const int* in_sizes, int n_in,
                              void* d_out, int out_size)
{
    (void)in_sizes; (void)n_in; (void)out_size;
    const float* x     = (const float*)d_in[0];
    const float* w_qkv = (const float*)d_in[1];
    const float* w_out = (const float*)d_in[2];
    float* out = (float*)d_out;

    __half *xh, *xl, *wq, *qkvh, *qkvl, *oh, *ol, *wo;
    cudaGetSymbolAddress((void**)&xh, g_xh);     cudaGetSymbolAddress((void**)&xl, g_xl);
    cudaGetSymbolAddress((void**)&wq, g_wq);
    cudaGetSymbolAddress((void**)&qkvh, g_qkvh); cudaGetSymbolAddress((void**)&qkvl, g_qkvl);
    cudaGetSymbolAddress((void**)&oh, g_oh);     cudaGetSymbolAddress((void**)&ol, g_ol);
    cudaGetSymbolAddress((void**)&wo, g_wo);

    cudaFuncSetAttribute(attn_mma,
                         cudaFuncAttributeMaxDynamicSharedMemorySize, ATTN_SMEM);
    cudaFuncSetAttribute(gemm_mma_h2<0>,
                         cudaFuncAttributeMaxDynamicSharedMemorySize, GEMM_SMEM);
    cudaFuncSetAttribute(gemm_mma_h2<1>,
                         cudaFuncAttributeMaxDynamicSharedMemorySize, GEMM_SMEM);

    // Splits / conversions
    {
        int n4 = (Mv * Dv) / 4;
        split_h<<<(n4 + 255) / 256, 256>>>(x, xh, xl, n4);
        n4 = (3 * Dv * Dv) / 4;
        cvt_h<<<(n4 + 255) / 256, 256>>>(w_qkv, wq, n4);
        n4 = (Dv * Dv) / 4;
        cvt_h<<<(n4 + 255) / 256, 256>>>(w_out, wo, n4);
    }

    // 1) QKV projection (2-pass fp16) -> fp16 hi/lo qkv
    gemm_mma_h2<1><<<GEMM_GRID, 128, GEMM_SMEM>>>(
        xh, xl, wq, nullptr, qkvh, qkvl, Mv, Dv, 3 * Dv);

    // 2) Causal flash attention (fp16x3) -> fp16 hi/lo O
    {
        dim3 g(Sv / BQa, Hv, Bv);
        attn_mma<<<g, 256, ATTN_SMEM>>>(qkvh, qkvl, oh, ol);
    }

    // 3) Output projection (2-pass fp16) -> fp32 out
    gemm_mma_h2<0><<<GEMM_GRID, 128, GEMM_SMEM>>>(
        oh, ol, wo, out, nullptr, nullptr, Mv, Dv, Dv);
}

// round 10
// speedup vs baseline: 1.3650x; 1.0933x over previous
#include <cuda_runtime.h>
#include <cuda_fp16.h>
#include <math.h>
#include <stdint.h>

// Problem constants
#define Bv 2
#define Sv 2048
#define Dv 1024
#define Hv 16
#define HDv 64
#define Mv (Bv*Sv)   // 4096 rows

// ---------------------------------------------------------------------------
// Scratch (device globals: no allocation allowed)
// ---------------------------------------------------------------------------
__device__ __align__(16) __half g_xh[(size_t)Mv * Dv];
__device__ __align__(16) __half g_xl[(size_t)Mv * Dv];
__device__ __align__(16) __half g_wq[(size_t)3 * Dv * Dv];
__device__ __align__(16) __half g_qkvh[(size_t)Mv * 3 * Dv];
__device__ __align__(16) __half g_qkvl[(size_t)Mv * 3 * Dv];
__device__ __align__(16) __half g_oh[(size_t)Mv * Dv];
__device__ __align__(16) __half g_ol[(size_t)Mv * Dv];
__device__ __align__(16) __half g_wo[(size_t)Dv * Dv];

// ---------------------------------------------------------------------------
// PTX helpers
// ---------------------------------------------------------------------------
__device__ __forceinline__ uint32_t smem_u32(const void* p) {
    uint32_t a;
    asm("{ .reg .u64 t; cvta.to.shared.u64 t, %1; cvt.u32.u64 %0, t; }" : "=r"(a) : "l"(p));
    return a;
}
#define CP_ASYNC16(sm, g) \
    asm volatile("cp.async.cg.shared.global [%0], [%1], 16;" :: "r"(sm), "l"(g) : "memory")
#define CP_COMMIT() asm volatile("cp.async.commit_group;" ::: "memory")
#define CP_WAIT(n)  asm volatile("cp.async.wait_group %0;" :: "n"(n) : "memory")

#define LDSM_X4(r0, r1, r2, r3, addr) \
    asm volatile("ldmatrix.sync.aligned.m8n8.x4.shared.b16 {%0,%1,%2,%3}, [%4];" \
        : "=r"(r0), "=r"(r1), "=r"(r2), "=r"(r3) : "r"(addr))
#define LDSM_X4_T(r0, r1, r2, r3, addr) \
    asm volatile("ldmatrix.sync.aligned.m8n8.x4.trans.shared.b16 {%0,%1,%2,%3}, [%4];" \
        : "=r"(r0), "=r"(r1), "=r"(r2), "=r"(r3) : "r"(addr))

// fp16 mma, fp32 accumulate
#define MMAH(d, a, b) \
    asm volatile("mma.sync.aligned.m16n8k16.row.col.f32.f16.f16.f32 " \
        "{%0,%1,%2,%3}, {%4,%5,%6,%7}, {%8,%9}, {%0,%1,%2,%3};" \
        : "+f"((d)[0]), "+f"((d)[1]), "+f"((d)[2]), "+f"((d)[3]) \
        : "r"((a)[0]), "r"((a)[1]), "r"((a)[2]), "r"((a)[3]), "r"((b)[0]), "r"((b)[1]))

// pack(lo, hi) -> f16x2 register (lo in low 16 bits)
__device__ __forceinline__ uint32_t packh(float lo, float hi) {
    __half2 h = __floats2half2_rn(lo, hi);
    return *reinterpret_cast<uint32_t*>(&h);
}
// residual of a prior packh
__device__ __forceinline__ uint32_t packresh(uint32_t h, float lo, float hi) {
    __half2 hh = *reinterpret_cast<__half2*>(&h);
    return packh(lo - __low2float(hh), hi - __high2float(hh));
}

// ---------------------------------------------------------------------------
// fp32 -> (fp16 hi, fp16 lo residual)
// ---------------------------------------------------------------------------
__global__ __launch_bounds__(256) void split_h(
    const float* __restrict__ in, __half* __restrict__ hi,
    __half* __restrict__ lo, int n4)
{
    int i = blockIdx.x * blockDim.x + threadIdx.x;
    if (i >= n4) return;
    float4 v = ((const float4*)in)[i];
    uint32_t h0 = packh(v.x, v.y), h1 = packh(v.z, v.w);
    uint32_t l0 = packresh(h0, v.x, v.y), l1 = packresh(h1, v.z, v.w);
    ((uint2*)hi)[i] = make_uint2(h0, h1);
    ((uint2*)lo)[i] = make_uint2(l0, l1);
}

// fp32 -> fp16 (single)
__global__ __launch_bounds__(256) void cvt_h(
    const float* __restrict__ in, __half* __restrict__ out, int n4)
{
    int i = blockIdx.x * blockDim.x + threadIdx.x;
    if (i >= n4) return;
    float4 v = ((const float4*)in)[i];
    ((uint2*)out)[i] = make_uint2(packh(v.x, v.y), packh(v.z, v.w));
}

// ---------------------------------------------------------------------------
// Persistent mma.sync fp16x2 GEMM:  C[M,N] = A[M,K] * B[N,K]^T
//   pass 1: Ah*B, pass 2: Al*B   (B single fp16)
// 128x128x32 CTA tile, 128 threads = 4 warps (64x64 each).
// ---------------------------------------------------------------------------
#define BM 128
#define BN 128
#define BKc 32
#define TILE_BYT (128 * 80)           // 80B row stride
#define STAGE_BYT (3 * TILE_BYT)      // Ah, Al, B
#define GEMM_SMEM (2 * STAGE_BYT)     // 61440 B
#define GEMM_GRID 296

__device__ __forceinline__ void load_stage(
    uint32_t sb, int s,
    const __half* __restrict__ Ah, const __half* __restrict__ Al,
    const __half* __restrict__ B,
    int bm, int bn, int k0, int K, int tid)
{
    const __half* srcs[3] = {
        Ah + (size_t)bm * K, Al + (size_t)bm * K, B + (size_t)bn * K };
    uint32_t base = sb + s * STAGE_BYT;
    #pragma unroll
    for (int t = 0; t < 3; ++t) {
        const __half* src = srcs[t];
        uint32_t tb = base + t * TILE_BYT;
        #pragma unroll
        for (int j = 0; j < 4; ++j) {
            int idx = tid + j * 128;            // 0..511
            int row = idx >> 2, ch = idx & 3;
            CP_ASYNC16(tb + row * 80 + ch * 16,
                       src + (size_t)row * K + k0 + ch * 8);
        }
    }
}

template<int WB>
__global__ __launch_bounds__(128) void gemm_mma_h2(
    const __half* __restrict__ Ah, const __half* __restrict__ Al,
    const __half* __restrict__ B,
    float* __restrict__ C, __half* __restrict__ Ch,
    __half* __restrict__ Cl, int M, int K, int N)
{
    extern __shared__ char smem[];
    const uint32_t sb = smem_u32(smem);
    const int tid = threadIdx.x, wid = tid >> 5, lane = tid & 31;
    const int wm = (wid >> 1) * 64;
    const int wn = (wid & 1) * 64;
    const uint32_t lrow = (lane & 15);
    const uint32_t lcol = (lane >> 4) * 16;
    const int ntn = N / BN;
    const int ntot = (M / BM) * ntn;
    const int NKB = K / BKc;

    for (int tix = blockIdx.x; tix < ntot; tix += (int)gridDim.x) {
        const int bm = (tix / ntn) * BM, bn = (tix % ntn) * BN;

        float acc[4][8][4];
        #pragma unroll
        for (int i = 0; i < 4; ++i)
            #pragma unroll
            for (int j = 0; j < 8; ++j)
                #pragma unroll
                for (int q = 0; q < 4; ++q) acc[i][j][q] = 0.f;

        load_stage(sb, 0, Ah, Al, B, bm, bn, 0, K, tid);
        CP_COMMIT();

        for (int kb = 0; kb < NKB; ++kb) {
            const int s = kb & 1;
            if (kb + 1 < NKB) {
                load_stage(sb, s ^ 1, Ah, Al, B, bm, bn, (kb + 1) * BKc, K, tid);
                CP_COMMIT();
                CP_WAIT(1);
            } else {
                CP_WAIT(0);
            }
            __syncthreads();

            const uint32_t stb = sb + s * STAGE_BYT;
            #pragma unroll
            for (int ks = 0; ks < 2; ++ks) {
                const uint32_t koff = ks * 32 + lcol;
                uint32_t ah[4][4], al[4][4], bb[4][4];
                #pragma unroll
                for (int rt = 0; rt < 4; ++rt) {
                    uint32_t ro = (wm + rt * 16 + lrow) * 80 + koff;
                    LDSM_X4(ah[rt][0], ah[rt][1], ah[rt][2], ah[rt][3], stb + ro);
                    LDSM_X4(al[rt][0], al[rt][1], al[rt][2], al[rt][3], stb + TILE_BYT + ro);
                }
                #pragma unroll
                for (int g = 0; g < 4; ++g) {
                    uint32_t ro = (wn + g * 16 + lrow) * 80 + koff;
                    LDSM_X4(bb[g][0], bb[g][1], bb[g][2], bb[g][3], stb + 2 * TILE_BYT + ro);
                }
                // pass 1: Ah*B
                #pragma unroll
                for (int rt = 0; rt < 4; ++rt)
                    #pragma unroll
                    for (int g = 0; g < 4; ++g)
                        #pragma unroll
                        for (int sub = 0; sub < 2; ++sub) {
                            uint32_t bf[2] = { bb[g][sub], bb[g][sub + 2] };
                            MMAH(acc[rt][g * 2 + sub], ah[rt], bf);
                        }
                // pass 2: Al*B
                #pragma unroll
                for (int rt = 0; rt < 4; ++rt)
                    #pragma unroll
                    for (int g = 0; g < 4; ++g)
                        #pragma unroll
                        for (int sub = 0; sub < 2; ++sub) {
                            uint32_t bf[2] = { bb[g][sub], bb[g][sub + 2] };
                            MMAH(acc[rt][g * 2 + sub], al[rt], bf);
                        }
            }
            __syncthreads();
        }

        const int r0 = bm + wm + (lane >> 2);
        const int c0 = bn + wn + (lane & 3) * 2;
        #pragma unroll
        for (int rt = 0; rt < 4; ++rt)
            #pragma unroll
            for (int ct = 0; ct < 8; ++ct) {
                size_t i0 = (size_t)(r0 + rt * 16) * N + c0 + ct * 8;
                size_t i1 = i0 + (size_t)8 * N;
                if (WB) {
                    uint32_t p0 = packh(acc[rt][ct][0], acc[rt][ct][1]);
                    uint32_t p1 = packh(acc[rt][ct][2], acc[rt][ct][3]);
                    *(uint32_t*)&Ch[i0] = p0;
                    *(uint32_t*)&Ch[i1] = p1;
                    *(uint32_t*)&Cl[i0] = packresh(p0, acc[rt][ct][0], acc[rt][ct][1]);
                    *(uint32_t*)&Cl[i1] = packresh(p1, acc[rt][ct][2], acc[rt][ct][3]);
                } else {
                    *(float2*)&C[i0] = make_float2(acc[rt][ct][0], acc[rt][ct][1]);
                    *(float2*)&C[i1] = make_float2(acc[rt][ct][2], acc[rt][ct][3]);
                }
            }
    }
}

// ---------------------------------------------------------------------------
// Flash attention, fp16 2-pass each side. CTA: 128 q-rows x 128 kv tile.
//   S = Qh*Kh + Ql*Kh   (K single fp16)
//   O = Ph*Vh + Pl*Vh   (V single fp16)
// K/V single tiles -> KV smem & load traffic halved vs R9.
// ---------------------------------------------------------------------------
#define BQa 128
#define BKVa 128
#define TST 144
#define SQH 0
#define SQL (128 * TST)
#define KVB (2 * 128 * TST)
#define KVSTG (2 * 128 * TST)           // Kh + Vh only
#define ATTN_SMEM (KVB + 2 * KVSTG)     // 110592 B

__global__ __launch_bounds__(256) void attn_mma(
    const __half* __restrict__ qkvh, const __half* __restrict__ qkvl,
    __half* __restrict__ oh, __half* __restrict__ ol)
{
    extern __shared__ char smem[];
    const uint32_t sb = smem_u32(smem);
    const int tid = threadIdx.x, wid = tid >> 5, lane = tid & 31;
    const int qi = (int)gridDim.x - 1 - (int)blockIdx.x;   // heavy tiles first
    const int h = blockIdx.y, b = blockIdx.z;
    const int qbase = qi * BQa;
    const int wq = wid * 16;
    const uint32_t lrow = lane & 15, lcol = (lane >> 4) * 16;
    const size_t ld = 3 * Dv;

    // Load Q tile (hi, lo)
    {
        const size_t base = ((size_t)b * Sv + qbase) * ld + (size_t)h * HDv;
        #pragma unroll
        for (int i = 0; i < 8; ++i) {
            int idx = tid + i * 256;
            int t = idx >> 10, rr = (idx >> 3) & 127, ch = idx & 7;
            const __half* src = (t ? qkvl : qkvh) + base + (size_t)rr * ld + ch * 8;
            CP_ASYNC16(sb + (t ? SQL : SQH) + rr * TST + ch * 16, src);
        }
    }

    const int ntiles = qi + 1;
    // prologue: KV tile 0 -> stage 0 (Kh, Vh only; from qkvh)
    {
        const size_t kbase = ((size_t)b * Sv) * ld + Dv + (size_t)h * HDv;
        #pragma unroll
        for (int i = 0; i < 8; ++i) {
            int idx = tid + i * 256;            // 2 tiles * 128 rows * 8 chunks
            int t = idx >> 10, rr = (idx >> 3) & 127, ch = idx & 7;
            const __half* src = qkvh + kbase + (t ? Dv : 0) + (size_t)rr * ld + ch * 8;
            CP_ASYNC16(sb + KVB + t * (128 * TST) + rr * TST + ch * 16, src);
        }
    }
    CP_COMMIT();

    float s[16][4], o[8][4];
    #pragma unroll
    for (int t = 0; t < 8; ++t)
        #pragma unroll
        for (int e = 0; e < 4; ++e) o[t][e] = 0.f;
    float m0 = -1e30f, m1 = -1e30f, l0 = 0.f, l1 = 0.f;

    for (int j = 0; j < ntiles; ++j) {
        const int stg = j & 1;
        if (j + 1 < ntiles) {
            const size_t kbase = ((size_t)b * Sv + (size_t)(j + 1) * BKVa) * ld + Dv + (size_t)h * HDv;
            uint32_t s0 = sb + KVB + (stg ^ 1) * KVSTG;
            #pragma unroll
            for (int i = 0; i < 8; ++i) {
                int idx = tid + i * 256;
                int t = idx >> 10, rr = (idx >> 3) & 127, ch = idx & 7;
                const __half* src = qkvh + kbase + (t ? Dv : 0) + (size_t)rr * ld + ch * 8;
                CP_ASYNC16(s0 + t * (128 * TST) + rr * TST + ch * 16, src);
            }
            CP_COMMIT();
            CP_WAIT(1);
        } else {
            CP_WAIT(0);
        }
        __syncthreads();

        const uint32_t kh_b = sb + KVB + stg * KVSTG;
        const uint32_t vh_b = kh_b + 128 * TST;

        // S = Q K^T (2-pass), 16 n8-tiles
        #pragma unroll
        for (int t = 0; t < 16; ++t)
            #pragma unroll
            for (int e = 0; e < 4; ++e) s[t][e] = 0.f;
        #pragma unroll
        for (int dc = 0; dc < 4; ++dc) {
            uint32_t qoff = (wq + lrow) * TST + dc * 32 + lcol;
            uint32_t qh[4], ql[4];
            LDSM_X4(qh[0], qh[1], qh[2], qh[3], sb + SQH + qoff);
            LDSM_X4(ql[0], ql[1], ql[2], ql[3], sb + SQL + qoff);
            #pragma unroll
            for (int ng = 0; ng < 8; ++ng) {
                uint32_t koff = (ng * 16 + lrow) * TST + dc * 32 + lcol;
                uint32_t kh[4];
                LDSM_X4(kh[0], kh[1], kh[2], kh[3], kh_b + koff);
                uint32_t b0h[2] = { kh[0], kh[2] }, b1h[2] = { kh[1], kh[3] };
                MMAH(s[2 * ng],     qh, b0h);
                MMAH(s[2 * ng + 1], qh, b1h);
                MMAH(s[2 * ng],     ql, b0h);
                MMAH(s[2 * ng + 1], ql, b1h);
            }
        }

        // scale + causal mask (diagonal tile only)
        const int row0 = qbase + wq + (lane >> 2);
        if (j == ntiles - 1) {
            #pragma unroll
            for (int t = 0; t < 16; ++t) {
                int colb = j * BKVa + 8 * t + (lane & 3) * 2;
                #pragma unroll
                for (int e = 0; e < 4; ++e) {
                    int col = colb + (e & 1);
                    int row = (e < 2) ? row0 : row0 + 8;
                    s[t][e] = (col > row) ? -1e30f : s[t][e] * 0.125f;
                }
            }
        } else {
            #pragma unroll
            for (int t = 0; t < 16; ++t)
                #pragma unroll
                for (int e = 0; e < 4; ++e) s[t][e] *= 0.125f;
        }

        // online softmax
        float mx0 = -1e30f, mx1 = -1e30f;
        #pragma unroll
        for (int t = 0; t < 16; ++t) {
            mx0 = fmaxf(mx0, fmaxf(s[t][0], s[t][1]));
            mx1 = fmaxf(mx1, fmaxf(s[t][2], s[t][3]));
        }
        mx0 = fmaxf(mx0, __shfl_xor_sync(0xffffffffu, mx0, 1));
        mx0 = fmaxf(mx0, __shfl_xor_sync(0xffffffffu, mx0, 2));
        mx1 = fmaxf(mx1, __shfl_xor_sync(0xffffffffu, mx1, 1));
        mx1 = fmaxf(mx1, __shfl_xor_sync(0xffffffffu, mx1, 2));
        float mn0 = fmaxf(m0, mx0), mn1 = fmaxf(m1, mx1);
        float a0 = __expf(m0 - mn0), a1 = __expf(m1 - mn1);
        m0 = mn0; m1 = mn1;
        float rs0 = 0.f, rs1 = 0.f;
        #pragma unroll
        for (int t = 0; t < 16; ++t) {
            s[t][0] = __expf(s[t][0] - mn0);
            s[t][1] = __expf(s[t][1] - mn0);
            s[t][2] = __expf(s[t][2] - mn1);
            s[t][3] = __expf(s[t][3] - mn1);
            rs0 += s[t][0] + s[t][1];
            rs1 += s[t][2] + s[t][3];
        }
        #pragma unroll
        for (int t = 0; t < 8; ++t) {
            o[t][0] *= a0; o[t][1] *= a0; o[t][2] *= a1; o[t][3] *= a1;
        }
        rs0 += __shfl_xor_sync(0xffffffffu, rs0, 1);
        rs0 += __shfl_xor_sync(0xffffffffu, rs0, 2);
        rs1 += __shfl_xor_sync(0xffffffffu, rs1, 1);
        rs1 += __shfl_xor_sync(0xffffffffu, rs1, 2);
        l0 = l0 * a0 + rs0;
        l1 = l1 * a1 + rs1;

        // O += P V (2-pass: Ph*V + Pl*V; P hi/lo in registers)
        #pragma unroll
        for (int kc = 0; kc < 8; ++kc) {
            uint32_t pah[4], pal[4];
            pah[0] = packh(s[2 * kc][0], s[2 * kc][1]);
            pah[1] = packh(s[2 * kc][2], s[2 * kc][3]);
            pah[2] = packh(s[2 * kc + 1][0], s[2 * kc + 1][1]);
            pah[3] = packh(s[2 * kc + 1][2], s[2 * kc + 1][3]);
            pal[0] = packresh(pah[0], s[2 * kc][0], s[2 * kc][1]);
            pal[1] = packresh(pah[1], s[2 * kc][2], s[2 * kc][3]);
            pal[2] = packresh(pah[2], s[2 * kc + 1][0], s[2 * kc + 1][1]);
            pal[3] = packresh(pah[3], s[2 * kc + 1][2], s[2 * kc + 1][3]);
            #pragma unroll
            for (int ng = 0; ng < 4; ++ng) {
                uint32_t voff = (kc * 16 + lrow) * TST + ng * 32 + lcol;
                uint32_t vh[4];
                LDSM_X4_T(vh[0], vh[1], vh[2], vh[3], vh_b + voff);
                uint32_t bv0[2] = { vh[0], vh[1] }, bv1[2] = { vh[2], vh[3] };
                MMAH(o[2 * ng],     pah, bv0);
                MMAH(o[2 * ng + 1], pah, bv1);
                MMAH(o[2 * ng],     pal, bv0);
                MMAH(o[2 * ng + 1], pal, bv1);
            }
        }
        __syncthreads();
    }

    // epilogue: O/l -> fp16 hi/lo at [b*S + q][h*64 + n]
    const float i0 = 1.f / l0, i1 = 1.f / l1;
    const size_t r0 = (size_t)b * Sv + qbase + wq + (lane >> 2);
    const int cb = h * HDv + (lane & 3) * 2;
    #pragma unroll
    for (int t = 0; t < 8; ++t) {
        size_t ia = r0 * Dv + cb + 8 * t;
        size_t ib = ia + (size_t)8 * Dv;
        float f0 = o[t][0] * i0, f1 = o[t][1] * i0;
        float f2 = o[t][2] * i1, f3 = o[t][3] * i1;
        uint32_t p0 = packh(f0, f1), p1 = packh(f2, f3);
        *(uint32_t*)&oh[ia] = p0;
        *(uint32_t*)&oh[ib] = p1;
        *(uint32_t*)&ol[ia] = packresh(p0, f0, f1);
        *(uint32_t*)&ol[ib] = packresh(p1, f2, f3);
    }
}

// ---------------------------------------------------------------------------
extern "C" void kernel_launch(void* const* d_in, const int* in_sizes, int n_in,
                              void* d_out, int out_size)
{
    (void)in_sizes; (void)n_in; (void)out_size;
    const float* x     = (const float*)d_in[0];
    const float* w_qkv = (const float*)d_in[1];
    const float* w_out = (const float*)d_in[2];
    float* out = (float*)d_out;

    __half *xh, *xl, *wq, *qkvh, *qkvl, *oh, *ol, *wo;
    cudaGetSymbolAddress((void**)&xh, g_xh);     cudaGetSymbolAddress((void**)&xl, g_xl);
    cudaGetSymbolAddress((void**)&wq, g_wq);
    cudaGetSymbolAddress((void**)&qkvh, g_qkvh); cudaGetSymbolAddress((void**)&qkvl, g_qkvl);
    cudaGetSymbolAddress((void**)&oh, g_oh);     cudaGetSymbolAddress((void**)&ol, g_ol);
    cudaGetSymbolAddress((void**)&wo, g_wo);

    cudaFuncSetAttribute(attn_mma,
                         cudaFuncAttributeMaxDynamicSharedMemorySize, ATTN_SMEM);
    cudaFuncSetAttribute(gemm_mma_h2<0>,
                         cudaFuncAttributeMaxDynamicSharedMemorySize, GEMM_SMEM);
    cudaFuncSetAttribute(gemm_mma_h2<1>,
                         cudaFuncAttributeMaxDynamicSharedMemorySize, GEMM_SMEM);

    // Splits / conversions
    {
        int n4 = (Mv * Dv) / 4;
        split_h<<<(n4 + 255) / 256, 256>>>(x, xh, xl, n4);
        n4 = (3 * Dv * Dv) / 4;
        cvt_h<<<(n4 + 255) / 256, 256>>>(w_qkv, wq, n4);
        n4 = (Dv * Dv) / 4;
        cvt_h<<<(n4 + 255) / 256, 256>>>(w_out, wo, n4);
    }

    // 1) QKV projection (2-pass fp16) -> fp16 hi/lo qkv
    gemm_mma_h2<1><<<GEMM_GRID, 128, GEMM_SMEM>>>(
        xh, xl, wq, nullptr, qkvh, qkvl, Mv, Dv, 3 * Dv);

    // 2) Causal flash attention (2-pass QK, 2-pass PV) -> fp16 hi/lo O
    {
        dim3 g(Sv / BQa, Hv, Bv);
        attn_mma<<<g, 256, ATTN_SMEM>>>(qkvh, qkvl, oh, ol);
    }

    // 3) Output projection (2-pass fp16) -> fp32 out
    gemm_mma_h2<0><<<GEMM_GRID, 128, GEMM_SMEM>>>(
        oh, ol, wo, out, nullptr, nullptr, Mv, Dv, Dv);
}

// round 11
// speedup vs baseline: 1.6071x; 1.1774x over previous
#include <cuda_runtime.h>
#include <cuda_fp16.h>
#include <math.h>
#include <stdint.h>

// Problem constants
#define Bv 2
#define Sv 2048
#define Dv 1024
#define Hv 16
#define HDv 64
#define Mv (Bv*Sv)   // 4096 rows

// ---------------------------------------------------------------------------
// Scratch (device globals: no allocation allowed)
// ---------------------------------------------------------------------------
__device__ __align__(16) __half g_xh[(size_t)Mv * Dv];
__device__ __align__(16) __half g_xl[(size_t)Mv * Dv];
__device__ __align__(16) __half g_wq[(size_t)3 * Dv * Dv];
__device__ __align__(16) __half g_qkvh[(size_t)Mv * 3 * Dv];
__device__ __align__(16) __half g_qkvl[(size_t)Mv * 3 * Dv];
__device__ __align__(16) __half g_oh[(size_t)Mv * Dv];
__device__ __align__(16) __half g_wo[(size_t)Dv * Dv];

// ---------------------------------------------------------------------------
// PTX helpers
// ---------------------------------------------------------------------------
__device__ __forceinline__ uint32_t smem_u32(const void* p) {
    uint32_t a;
    asm("{ .reg .u64 t; cvta.to.shared.u64 t, %1; cvt.u32.u64 %0, t; }" : "=r"(a) : "l"(p));
    return a;
}
#define CP_ASYNC16(sm, g) \
    asm volatile("cp.async.cg.shared.global [%0], [%1], 16;" :: "r"(sm), "l"(g) : "memory")
#define CP_COMMIT() asm volatile("cp.async.commit_group;" ::: "memory")
#define CP_WAIT(n)  asm volatile("cp.async.wait_group %0;" :: "n"(n) : "memory")

#define LDSM_X4(r0, r1, r2, r3, addr) \
    asm volatile("ldmatrix.sync.aligned.m8n8.x4.shared.b16 {%0,%1,%2,%3}, [%4];" \
        : "=r"(r0), "=r"(r1), "=r"(r2), "=r"(r3) : "r"(addr))
#define LDSM_X4_T(r0, r1, r2, r3, addr) \
    asm volatile("ldmatrix.sync.aligned.m8n8.x4.trans.shared.b16 {%0,%1,%2,%3}, [%4];" \
        : "=r"(r0), "=r"(r1), "=r"(r2), "=r"(r3) : "r"(addr))

// fp16 mma, fp32 accumulate
#define MMAH(d, a, b) \
    asm volatile("mma.sync.aligned.m16n8k16.row.col.f32.f16.f16.f32 " \
        "{%0,%1,%2,%3}, {%4,%5,%6,%7}, {%8,%9}, {%0,%1,%2,%3};" \
        : "+f"((d)[0]), "+f"((d)[1]), "+f"((d)[2]), "+f"((d)[3]) \
        : "r"((a)[0]), "r"((a)[1]), "r"((a)[2]), "r"((a)[3]), "r"((b)[0]), "r"((b)[1]))

// pack(lo, hi) -> f16x2 register (lo in low 16 bits)
__device__ __forceinline__ uint32_t packh(float lo, float hi) {
    __half2 h = __floats2half2_rn(lo, hi);
    return *reinterpret_cast<uint32_t*>(&h);
}
// residual of a prior packh
__device__ __forceinline__ uint32_t packresh(uint32_t h, float lo, float hi) {
    __half2 hh = *reinterpret_cast<__half2*>(&h);
    return packh(lo - __low2float(hh), hi - __high2float(hh));
}

// ---------------------------------------------------------------------------
// fp32 -> (fp16 hi, fp16 lo residual)
// ---------------------------------------------------------------------------
__global__ __launch_bounds__(256) void split_h(
    const float* __restrict__ in, __half* __restrict__ hi,
    __half* __restrict__ lo, int n4)
{
    int i = blockIdx.x * blockDim.x + threadIdx.x;
    if (i >= n4) return;
    float4 v = ((const float4*)in)[i];
    uint32_t h0 = packh(v.x, v.y), h1 = packh(v.z, v.w);
    uint32_t l0 = packresh(h0, v.x, v.y), l1 = packresh(h1, v.z, v.w);
    ((uint2*)hi)[i] = make_uint2(h0, h1);
    ((uint2*)lo)[i] = make_uint2(l0, l1);
}

// fp32 -> fp16 (single)
__global__ __launch_bounds__(256) void cvt_h(
    const float* __restrict__ in, __half* __restrict__ out, int n4)
{
    int i = blockIdx.x * blockDim.x + threadIdx.x;
    if (i >= n4) return;
    float4 v = ((const float4*)in)[i];
    ((uint2*)out)[i] = make_uint2(packh(v.x, v.y), packh(v.z, v.w));
}

// ---------------------------------------------------------------------------
// Persistent mma.sync GEMM:  C[M,N] = A[M,K] * B[N,K]^T
//   NP=2: pass 1 Ah*B, pass 2 Al*B (activation hi/lo, weight single fp16)
//   NP=1: single pass Ah*B
// 128x128x32 CTA tile, 128 threads = 4 warps (64x64 each).
// ---------------------------------------------------------------------------
#define BM 128
#define BN 128
#define BKc 32
#define TILE_BYT (128 * 80)           // 80B row stride
#define STAGE_BYT (3 * TILE_BYT)      // slots: Ah, Al, B (Al unused if NP==1)
#define GEMM_SMEM (2 * STAGE_BYT)     // 61440 B
#define GEMM_GRID 296

template<int NP>
__device__ __forceinline__ void load_stage(
    uint32_t sb, int s,
    const __half* __restrict__ Ah, const __half* __restrict__ Al,
    const __half* __restrict__ B,
    int bm, int bn, int k0, int K, int tid)
{
    uint32_t base = sb + s * STAGE_BYT;
    #pragma unroll
    for (int j = 0; j < 4; ++j) {
        int idx = tid + j * 128;            // 0..511
        int row = idx >> 2, ch = idx & 3;
        CP_ASYNC16(base + row * 80 + ch * 16,
                   Ah + (size_t)(bm + row) * K + k0 + ch * 8);
        if (NP == 2)
            CP_ASYNC16(base + TILE_BYT + row * 80 + ch * 16,
                       Al + (size_t)(bm + row) * K + k0 + ch * 8);
        CP_ASYNC16(base + 2 * TILE_BYT + row * 80 + ch * 16,
                   B + (size_t)(bn + row) * K + k0 + ch * 8);
    }
}

template<int WB, int NP>
__global__ __launch_bounds__(128) void gemm_mma_h(
    const __half* __restrict__ Ah, const __half* __restrict__ Al,
    const __half* __restrict__ B,
    float* __restrict__ C, __half* __restrict__ Ch,
    __half* __restrict__ Cl, int M, int K, int N)
{
    extern __shared__ char smem[];
    const uint32_t sb = smem_u32(smem);
    const int tid = threadIdx.x, wid = tid >> 5, lane = tid & 31;
    const int wm = (wid >> 1) * 64;
    const int wn = (wid & 1) * 64;
    const uint32_t lrow = (lane & 15);
    const uint32_t lcol = (lane >> 4) * 16;
    const int ntn = N / BN;
    const int ntot = (M / BM) * ntn;
    const int NKB = K / BKc;

    for (int tix = blockIdx.x; tix < ntot; tix += (int)gridDim.x) {
        const int bm = (tix / ntn) * BM, bn = (tix % ntn) * BN;

        float acc[4][8][4];
        #pragma unroll
        for (int i = 0; i < 4; ++i)
            #pragma unroll
            for (int j = 0; j < 8; ++j)
                #pragma unroll
                for (int q = 0; q < 4; ++q) acc[i][j][q] = 0.f;

        load_stage<NP>(sb, 0, Ah, Al, B, bm, bn, 0, K, tid);
        CP_COMMIT();

        for (int kb = 0; kb < NKB; ++kb) {
            const int s = kb & 1;
            if (kb + 1 < NKB) {
                load_stage<NP>(sb, s ^ 1, Ah, Al, B, bm, bn, (kb + 1) * BKc, K, tid);
                CP_COMMIT();
                CP_WAIT(1);
            } else {
                CP_WAIT(0);
            }
            __syncthreads();

            const uint32_t stb = sb + s * STAGE_BYT;
            #pragma unroll
            for (int ks = 0; ks < 2; ++ks) {
                const uint32_t koff = ks * 32 + lcol;
                uint32_t ah[4][4], al[4][4], bb[4][4];
                #pragma unroll
                for (int rt = 0; rt < 4; ++rt) {
                    uint32_t ro = (wm + rt * 16 + lrow) * 80 + koff;
                    LDSM_X4(ah[rt][0], ah[rt][1], ah[rt][2], ah[rt][3], stb + ro);
                    if (NP == 2)
                        LDSM_X4(al[rt][0], al[rt][1], al[rt][2], al[rt][3], stb + TILE_BYT + ro);
                }
                #pragma unroll
                for (int g = 0; g < 4; ++g) {
                    uint32_t ro = (wn + g * 16 + lrow) * 80 + koff;
                    LDSM_X4(bb[g][0], bb[g][1], bb[g][2], bb[g][3], stb + 2 * TILE_BYT + ro);
                }
                // pass 1: Ah*B
                #pragma unroll
                for (int rt = 0; rt < 4; ++rt)
                    #pragma unroll
                    for (int g = 0; g < 4; ++g)
                        #pragma unroll
                        for (int sub = 0; sub < 2; ++sub) {
                            uint32_t bf[2] = { bb[g][sub], bb[g][sub + 2] };
                            MMAH(acc[rt][g * 2 + sub], ah[rt], bf);
                        }
                // pass 2: Al*B
                if (NP == 2) {
                    #pragma unroll
                    for (int rt = 0; rt < 4; ++rt)
                        #pragma unroll
                        for (int g = 0; g < 4; ++g)
                            #pragma unroll
                            for (int sub = 0; sub < 2; ++sub) {
                                uint32_t bf[2] = { bb[g][sub], bb[g][sub + 2] };
                                MMAH(acc[rt][g * 2 + sub], al[rt], bf);
                            }
                }
            }
            __syncthreads();
        }

        const int r0 = bm + wm + (lane >> 2);
        const int c0 = bn + wn + (lane & 3) * 2;
        #pragma unroll
        for (int rt = 0; rt < 4; ++rt)
            #pragma unroll
            for (int ct = 0; ct < 8; ++ct) {
                size_t i0 = (size_t)(r0 + rt * 16) * N + c0 + ct * 8;
                size_t i1 = i0 + (size_t)8 * N;
                if (WB) {
                    uint32_t p0 = packh(acc[rt][ct][0], acc[rt][ct][1]);
                    uint32_t p1 = packh(acc[rt][ct][2], acc[rt][ct][3]);
                    *(uint32_t*)&Ch[i0] = p0;
                    *(uint32_t*)&Ch[i1] = p1;
                    *(uint32_t*)&Cl[i0] = packresh(p0, acc[rt][ct][0], acc[rt][ct][1]);
                    *(uint32_t*)&Cl[i1] = packresh(p1, acc[rt][ct][2], acc[rt][ct][3]);
                } else {
                    *(float2*)&C[i0] = make_float2(acc[rt][ct][0], acc[rt][ct][1]);
                    *(float2*)&C[i1] = make_float2(acc[rt][ct][2], acc[rt][ct][3]);
                }
            }
    }
}

// ---------------------------------------------------------------------------
// Flash attention. CTA: 128 q-rows x 128 kv tile, 8 warps.
//   S = Qh*Kh + Ql*Kh   (K single fp16, Q hi/lo)
//   O = Ph*Vh           (single pass; P rounding rel err ~2^-11/sqrt(3))
// ---------------------------------------------------------------------------
#define BQa 128
#define BKVa 128
#define TST 144
#define SQH 0
#define SQL (128 * TST)
#define KVB (2 * 128 * TST)
#define KVSTG (2 * 128 * TST)           // Kh + Vh
#define ATTN_SMEM (KVB + 2 * KVSTG)     // 110592 B

__global__ __launch_bounds__(256) void attn_mma(
    const __half* __restrict__ qkvh, const __half* __restrict__ qkvl,
    __half* __restrict__ oh)
{
    extern __shared__ char smem[];
    const uint32_t sb = smem_u32(smem);
    const int tid = threadIdx.x, wid = tid >> 5, lane = tid & 31;
    const int qi = (int)gridDim.x - 1 - (int)blockIdx.x;   // heavy tiles first
    const int h = blockIdx.y, b = blockIdx.z;
    const int qbase = qi * BQa;
    const int wq = wid * 16;
    const uint32_t lrow = lane & 15, lcol = (lane >> 4) * 16;
    const size_t ld = 3 * Dv;

    // Load Q tile (hi, lo)
    {
        const size_t base = ((size_t)b * Sv + qbase) * ld + (size_t)h * HDv;
        #pragma unroll
        for (int i = 0; i < 8; ++i) {
            int idx = tid + i * 256;
            int t = idx >> 10, rr = (idx >> 3) & 127, ch = idx & 7;
            const __half* src = (t ? qkvl : qkvh) + base + (size_t)rr * ld + ch * 8;
            CP_ASYNC16(sb + (t ? SQL : SQH) + rr * TST + ch * 16, src);
        }
    }

    const int ntiles = qi + 1;
    // prologue: KV tile 0 -> stage 0 (Kh, Vh from qkvh)
    {
        const size_t kbase = ((size_t)b * Sv) * ld + Dv + (size_t)h * HDv;
        #pragma unroll
        for (int i = 0; i < 8; ++i) {
            int idx = tid + i * 256;
            int t = idx >> 10, rr = (idx >> 3) & 127, ch = idx & 7;
            const __half* src = qkvh + kbase + (t ? Dv : 0) + (size_t)rr * ld + ch * 8;
            CP_ASYNC16(sb + KVB + t * (128 * TST) + rr * TST + ch * 16, src);
        }
    }
    CP_COMMIT();

    float s[16][4], o[8][4];
    #pragma unroll
    for (int t = 0; t < 8; ++t)
        #pragma unroll
        for (int e = 0; e < 4; ++e) o[t][e] = 0.f;
    float m0 = -1e30f, m1 = -1e30f, l0 = 0.f, l1 = 0.f;

    for (int j = 0; j < ntiles; ++j) {
        const int stg = j & 1;
        if (j + 1 < ntiles) {
            const size_t kbase = ((size_t)b * Sv + (size_t)(j + 1) * BKVa) * ld + Dv + (size_t)h * HDv;
            uint32_t s0 = sb + KVB + (stg ^ 1) * KVSTG;
            #pragma unroll
            for (int i = 0; i < 8; ++i) {
                int idx = tid + i * 256;
                int t = idx >> 10, rr = (idx >> 3) & 127, ch = idx & 7;
                const __half* src = qkvh + kbase + (t ? Dv : 0) + (size_t)rr * ld + ch * 8;
                CP_ASYNC16(s0 + t * (128 * TST) + rr * TST + ch * 16, src);
            }
            CP_COMMIT();
            CP_WAIT(1);
        } else {
            CP_WAIT(0);
        }
        __syncthreads();

        const uint32_t kh_b = sb + KVB + stg * KVSTG;
        const uint32_t vh_b = kh_b + 128 * TST;

        // S = Q K^T (2-pass), 16 n8-tiles
        #pragma unroll
        for (int t = 0; t < 16; ++t)
            #pragma unroll
            for (int e = 0; e < 4; ++e) s[t][e] = 0.f;
        #pragma unroll
        for (int dc = 0; dc < 4; ++dc) {
            uint32_t qoff = (wq + lrow) * TST + dc * 32 + lcol;
            uint32_t qh[4], ql[4];
            LDSM_X4(qh[0], qh[1], qh[2], qh[3], sb + SQH + qoff);
            LDSM_X4(ql[0], ql[1], ql[2], ql[3], sb + SQL + qoff);
            #pragma unroll
            for (int ng = 0; ng < 8; ++ng) {
                uint32_t koff = (ng * 16 + lrow) * TST + dc * 32 + lcol;
                uint32_t kh[4];
                LDSM_X4(kh[0], kh[1], kh[2], kh[3], kh_b + koff);
                uint32_t b0h[2] = { kh[0], kh[2] }, b1h[2] = { kh[1], kh[3] };
                MMAH(s[2 * ng],     qh, b0h);
                MMAH(s[2 * ng + 1], qh, b1h);
                MMAH(s[2 * ng],     ql, b0h);
                MMAH(s[2 * ng + 1], ql, b1h);
            }
        }

        // scale + causal mask (diagonal tile only)
        const int row0 = qbase + wq + (lane >> 2);
        if (j == ntiles - 1) {
            #pragma unroll
            for (int t = 0; t < 16; ++t) {
                int colb = j * BKVa + 8 * t + (lane & 3) * 2;
                #pragma unroll
                for (int e = 0; e < 4; ++e) {
                    int col = colb + (e & 1);
                    int row = (e < 2) ? row0 : row0 + 8;
                    s[t][e] = (col > row) ? -1e30f : s[t][e] * 0.125f;
                }
            }
        } else {
            #pragma unroll
            for (int t = 0; t < 16; ++t)
                #pragma unroll
                for (int e = 0; e < 4; ++e) s[t][e] *= 0.125f;
        }

        // online softmax
        float mx0 = -1e30f, mx1 = -1e30f;
        #pragma unroll
        for (int t = 0; t < 16; ++t) {
            mx0 = fmaxf(mx0, fmaxf(s[t][0], s[t][1]));
            mx1 = fmaxf(mx1, fmaxf(s[t][2], s[t][3]));
        }
        mx0 = fmaxf(mx0, __shfl_xor_sync(0xffffffffu, mx0, 1));
        mx0 = fmaxf(mx0, __shfl_xor_sync(0xffffffffu, mx0, 2));
        mx1 = fmaxf(mx1, __shfl_xor_sync(0xffffffffu, mx1, 1));
        mx1 = fmaxf(mx1, __shfl_xor_sync(0xffffffffu, mx1, 2));
        float mn0 = fmaxf(m0, mx0), mn1 = fmaxf(m1, mx1);
        float a0 = __expf(m0 - mn0), a1 = __expf(m1 - mn1);
        m0 = mn0; m1 = mn1;
        float rs0 = 0.f, rs1 = 0.f;
        #pragma unroll
        for (int t = 0; t < 16; ++t) {
            s[t][0] = __expf(s[t][0] - mn0);
            s[t][1] = __expf(s[t][1] - mn0);
            s[t][2] = __expf(s[t][2] - mn1);
            s[t][3] = __expf(s[t][3] - mn1);
            rs0 += s[t][0] + s[t][1];
            rs1 += s[t][2] + s[t][3];
        }
        #pragma unroll
        for (int t = 0; t < 8; ++t) {
            o[t][0] *= a0; o[t][1] *= a0; o[t][2] *= a1; o[t][3] *= a1;
        }
        rs0 += __shfl_xor_sync(0xffffffffu, rs0, 1);
        rs0 += __shfl_xor_sync(0xffffffffu, rs0, 2);
        rs1 += __shfl_xor_sync(0xffffffffu, rs1, 1);
        rs1 += __shfl_xor_sync(0xffffffffu, rs1, 2);
        l0 = l0 * a0 + rs0;
        l1 = l1 * a1 + rs1;

        // O += P V (single pass: Ph*Vh)
        #pragma unroll
        for (int kc = 0; kc < 8; ++kc) {
            uint32_t pah[4];
            pah[0] = packh(s[2 * kc][0], s[2 * kc][1]);
            pah[1] = packh(s[2 * kc][2], s[2 * kc][3]);
            pah[2] = packh(s[2 * kc + 1][0], s[2 * kc + 1][1]);
            pah[3] = packh(s[2 * kc + 1][2], s[2 * kc + 1][3]);
            #pragma unroll
            for (int ng = 0; ng < 4; ++ng) {
                uint32_t voff = (kc * 16 + lrow) * TST + ng * 32 + lcol;
                uint32_t vh[4];
                LDSM_X4_T(vh[0], vh[1], vh[2], vh[3], vh_b + voff);
                uint32_t bv0[2] = { vh[0], vh[1] }, bv1[2] = { vh[2], vh[3] };
                MMAH(o[2 * ng],     pah, bv0);
                MMAH(o[2 * ng + 1], pah, bv1);
            }
        }
        __syncthreads();
    }

    // epilogue: O/l -> fp16 at [b*S + q][h*64 + n]
    const float i0 = 1.f / l0, i1 = 1.f / l1;
    const size_t r0 = (size_t)b * Sv + qbase + wq + (lane >> 2);
    const int cb = h * HDv + (lane & 3) * 2;
    #pragma unroll
    for (int t = 0; t < 8; ++t) {
        size_t ia = r0 * Dv + cb + 8 * t;
        size_t ib = ia + (size_t)8 * Dv;
        *(uint32_t*)&oh[ia] = packh(o[t][0] * i0, o[t][1] * i0);
        *(uint32_t*)&oh[ib] = packh(o[t][2] * i1, o[t][3] * i1);
    }
}

// ---------------------------------------------------------------------------
extern "C" void kernel_launch(void* const* d_in, const int* in_sizes, int n_in,
                              void* d_out, int out_size)
{
    (void)in_sizes; (void)n_in; (void)out_size;
    const float* x     = (const float*)d_in[0];
    const float* w_qkv = (const float*)d_in[1];
    const float* w_out = (const float*)d_in[2];
    float* out = (float*)d_out;

    __half *xh, *xl, *wq, *qkvh, *qkvl, *oh, *wo;
    cudaGetSymbolAddress((void**)&xh, g_xh);     cudaGetSymbolAddress((void**)&xl, g_xl);
    cudaGetSymbolAddress((void**)&wq, g_wq);
    cudaGetSymbolAddress((void**)&qkvh, g_qkvh); cudaGetSymbolAddress((void**)&qkvl, g_qkvl);
    cudaGetSymbolAddress((void**)&oh, g_oh);
    cudaGetSymbolAddress((void**)&wo, g_wo);

    cudaFuncSetAttribute(attn_mma,
                         cudaFuncAttributeMaxDynamicSharedMemorySize, ATTN_SMEM);
    cudaFuncSetAttribute(gemm_mma_h<1, 2>,
                         cudaFuncAttributeMaxDynamicSharedMemorySize, GEMM_SMEM);
    cudaFuncSetAttribute(gemm_mma_h<0, 1>,
                         cudaFuncAttributeMaxDynamicSharedMemorySize, GEMM_SMEM);

    // Splits / conversions
    {
        int n4 = (Mv * Dv) / 4;
        split_h<<<(n4 + 255) / 256, 256>>>(x, xh, xl, n4);
        n4 = (3 * Dv * Dv) / 4;
        cvt_h<<<(n4 + 255) / 256, 256>>>(w_qkv, wq, n4);
        n4 = (Dv * Dv) / 4;
        cvt_h<<<(n4 + 255) / 256, 256>>>(w_out, wo, n4);
    }

    // 1) QKV projection (2-pass fp16) -> fp16 hi/lo qkv
    gemm_mma_h<1, 2><<<GEMM_GRID, 128, GEMM_SMEM>>>(
        xh, xl, wq, nullptr, qkvh, qkvl, Mv, Dv, 3 * Dv);

    // 2) Causal flash attention (2-pass QK, 1-pass PV) -> fp16 O
    {
        dim3 g(Sv / BQa, Hv, Bv);
        attn_mma<<<g, 256, ATTN_SMEM>>>(qkvh, qkvl, oh);
    }

    // 3) Output projection (1-pass fp16) -> fp32 out
    gemm_mma_h<0, 1><<<GEMM_GRID, 128, GEMM_SMEM>>>(
        oh, nullptr, wo, out, nullptr, nullptr, Mv, Dv, Dv);
}

// round 12
// speedup vs baseline: 2.1509x; 1.3384x over previous
#include <cuda_runtime.h>
#include <cuda_fp16.h>
#include <math.h>
#include <stdint.h>

// Problem constants
#define Bv 2
#define Sv 2048
#define Dv 1024
#define Hv 16
#define HDv 64
#define Mv (Bv*Sv)   // 4096 rows

// ---------------------------------------------------------------------------
// Scratch (device globals: no allocation allowed)
// ---------------------------------------------------------------------------
__device__ __align__(16) __half g_xh[(size_t)Mv * Dv];
__device__ __align__(16) __half g_wq[(size_t)3 * Dv * Dv];
__device__ __align__(16) __half g_qkvh[(size_t)Mv * 3 * Dv];
__device__ __align__(16) __half g_qkvl[(size_t)Mv * 3 * Dv];
__device__ __align__(16) __half g_oh[(size_t)Mv * Dv];
__device__ __align__(16) __half g_wo[(size_t)Dv * Dv];

// ---------------------------------------------------------------------------
// PTX helpers
// ---------------------------------------------------------------------------
__device__ __forceinline__ uint32_t smem_u32(const void* p) {
    uint32_t a;
    asm("{ .reg .u64 t; cvta.to.shared.u64 t, %1; cvt.u32.u64 %0, t; }" : "=r"(a) : "l"(p));
    return a;
}
#define CP_ASYNC16(sm, g) \
    asm volatile("cp.async.cg.shared.global [%0], [%1], 16;" :: "r"(sm), "l"(g) : "memory")
#define CP_COMMIT() asm volatile("cp.async.commit_group;" ::: "memory")
#define CP_WAIT(n)  asm volatile("cp.async.wait_group %0;" :: "n"(n) : "memory")

#define LDSM_X4(r0, r1, r2, r3, addr) \
    asm volatile("ldmatrix.sync.aligned.m8n8.x4.shared.b16 {%0,%1,%2,%3}, [%4];" \
        : "=r"(r0), "=r"(r1), "=r"(r2), "=r"(r3) : "r"(addr))
#define LDSM_X4_T(r0, r1, r2, r3, addr) \
    asm volatile("ldmatrix.sync.aligned.m8n8.x4.trans.shared.b16 {%0,%1,%2,%3}, [%4];" \
        : "=r"(r0), "=r"(r1), "=r"(r2), "=r"(r3) : "r"(addr))

// fp16 mma, fp32 accumulate
#define MMAH(d, a, b) \
    asm volatile("mma.sync.aligned.m16n8k16.row.col.f32.f16.f16.f32 " \
        "{%0,%1,%2,%3}, {%4,%5,%6,%7}, {%8,%9}, {%0,%1,%2,%3};" \
        : "+f"((d)[0]), "+f"((d)[1]), "+f"((d)[2]), "+f"((d)[3]) \
        : "r"((a)[0]), "r"((a)[1]), "r"((a)[2]), "r"((a)[3]), "r"((b)[0]), "r"((b)[1]))

// pack(lo, hi) -> f16x2 register (lo in low 16 bits)
__device__ __forceinline__ uint32_t packh(float lo, float hi) {
    __half2 h = __floats2half2_rn(lo, hi);
    return *reinterpret_cast<uint32_t*>(&h);
}
// residual of a prior packh
__device__ __forceinline__ uint32_t packresh(uint32_t h, float lo, float hi) {
    __half2 hh = *reinterpret_cast<__half2*>(&h);
    return packh(lo - __low2float(hh), hi - __high2float(hh));
}

// ---------------------------------------------------------------------------
// fp32 -> fp16 (single)
// ---------------------------------------------------------------------------
__global__ __launch_bounds__(256) void cvt_h(
    const float* __restrict__ in, __half* __restrict__ out, int n4)
{
    int i = blockIdx.x * blockDim.x + threadIdx.x;
    if (i >= n4) return;
    float4 v = ((const float4*)in)[i];
    ((uint2*)out)[i] = make_uint2(packh(v.x, v.y), packh(v.z, v.w));
}

// ---------------------------------------------------------------------------
// Persistent mma.sync GEMM:  C[M,N] = A[M,K] * B[N,K]^T
//   NP=2: pass 1 Ah*B, pass 2 Al*B;  NP=1: single pass Ah*B
// 128x128x32 CTA tile, 128 threads = 4 warps (64x64 each).
// ---------------------------------------------------------------------------
#define BM 128
#define BN 128
#define BKc 32
#define TILE_BYT (128 * 80)           // 80B row stride
#define STAGE_BYT (3 * TILE_BYT)      // slots: Ah, Al, B (Al unused if NP==1)
#define GEMM_SMEM (2 * STAGE_BYT)     // 61440 B
#define GEMM_GRID 296

template<int NP>
__device__ __forceinline__ void load_stage(
    uint32_t sb, int s,
    const __half* __restrict__ Ah, const __half* __restrict__ Al,
    const __half* __restrict__ B,
    int bm, int bn, int k0, int K, int tid)
{
    uint32_t base = sb + s * STAGE_BYT;
    #pragma unroll
    for (int j = 0; j < 4; ++j) {
        int idx = tid + j * 128;            // 0..511
        int row = idx >> 2, ch = idx & 3;
        CP_ASYNC16(base + row * 80 + ch * 16,
                   Ah + (size_t)(bm + row) * K + k0 + ch * 8);
        if (NP == 2)
            CP_ASYNC16(base + TILE_BYT + row * 80 + ch * 16,
                       Al + (size_t)(bm + row) * K + k0 + ch * 8);
        CP_ASYNC16(base + 2 * TILE_BYT + row * 80 + ch * 16,
                   B + (size_t)(bn + row) * K + k0 + ch * 8);
    }
}

template<int WB, int NP>
__global__ __launch_bounds__(128) void gemm_mma_h(
    const __half* __restrict__ Ah, const __half* __restrict__ Al,
    const __half* __restrict__ B,
    float* __restrict__ C, __half* __restrict__ Ch,
    __half* __restrict__ Cl, int M, int K, int N)
{
    extern __shared__ char smem[];
    const uint32_t sb = smem_u32(smem);
    const int tid = threadIdx.x, wid = tid >> 5, lane = tid & 31;
    const int wm = (wid >> 1) * 64;
    const int wn = (wid & 1) * 64;
    const uint32_t lrow = (lane & 15);
    const uint32_t lcol = (lane >> 4) * 16;
    const int ntn = N / BN;
    const int ntot = (M / BM) * ntn;
    const int NKB = K / BKc;

    for (int tix = blockIdx.x; tix < ntot; tix += (int)gridDim.x) {
        const int bm = (tix / ntn) * BM, bn = (tix % ntn) * BN;

        float acc[4][8][4];
        #pragma unroll
        for (int i = 0; i < 4; ++i)
            #pragma unroll
            for (int j = 0; j < 8; ++j)
                #pragma unroll
                for (int q = 0; q < 4; ++q) acc[i][j][q] = 0.f;

        load_stage<NP>(sb, 0, Ah, Al, B, bm, bn, 0, K, tid);
        CP_COMMIT();

        for (int kb = 0; kb < NKB; ++kb) {
            const int s = kb & 1;
            if (kb + 1 < NKB) {
                load_stage<NP>(sb, s ^ 1, Ah, Al, B, bm, bn, (kb + 1) * BKc, K, tid);
                CP_COMMIT();
                CP_WAIT(1);
            } else {
                CP_WAIT(0);
            }
            __syncthreads();

            const uint32_t stb = sb + s * STAGE_BYT;
            #pragma unroll
            for (int ks = 0; ks < 2; ++ks) {
                const uint32_t koff = ks * 32 + lcol;
                uint32_t ah[4][4], al[4][4], bb[4][4];
                #pragma unroll
                for (int rt = 0; rt < 4; ++rt) {
                    uint32_t ro = (wm + rt * 16 + lrow) * 80 + koff;
                    LDSM_X4(ah[rt][0], ah[rt][1], ah[rt][2], ah[rt][3], stb + ro);
                    if (NP == 2)
                        LDSM_X4(al[rt][0], al[rt][1], al[rt][2], al[rt][3], stb + TILE_BYT + ro);
                }
                #pragma unroll
                for (int g = 0; g < 4; ++g) {
                    uint32_t ro = (wn + g * 16 + lrow) * 80 + koff;
                    LDSM_X4(bb[g][0], bb[g][1], bb[g][2], bb[g][3], stb + 2 * TILE_BYT + ro);
                }
                // pass 1: Ah*B
                #pragma unroll
                for (int rt = 0; rt < 4; ++rt)
                    #pragma unroll
                    for (int g = 0; g < 4; ++g)
                        #pragma unroll
                        for (int sub = 0; sub < 2; ++sub) {
                            uint32_t bf[2] = { bb[g][sub], bb[g][sub + 2] };
                            MMAH(acc[rt][g * 2 + sub], ah[rt], bf);
                        }
                // pass 2: Al*B
                if (NP == 2) {
                    #pragma unroll
                    for (int rt = 0; rt < 4; ++rt)
                        #pragma unroll
                        for (int g = 0; g < 4; ++g)
                            #pragma unroll
                            for (int sub = 0; sub < 2; ++sub) {
                                uint32_t bf[2] = { bb[g][sub], bb[g][sub + 2] };
                                MMAH(acc[rt][g * 2 + sub], al[rt], bf);
                            }
                }
            }
            __syncthreads();
        }

        const int r0 = bm + wm + (lane >> 2);
        const int c0 = bn + wn + (lane & 3) * 2;
        #pragma unroll
        for (int rt = 0; rt < 4; ++rt)
            #pragma unroll
            for (int ct = 0; ct < 8; ++ct) {
                size_t i0 = (size_t)(r0 + rt * 16) * N + c0 + ct * 8;
                size_t i1 = i0 + (size_t)8 * N;
                if (WB) {
                    uint32_t p0 = packh(acc[rt][ct][0], acc[rt][ct][1]);
                    uint32_t p1 = packh(acc[rt][ct][2], acc[rt][ct][3]);
                    *(uint32_t*)&Ch[i0] = p0;
                    *(uint32_t*)&Ch[i1] = p1;
                    *(uint32_t*)&Cl[i0] = packresh(p0, acc[rt][ct][0], acc[rt][ct][1]);
                    *(uint32_t*)&Cl[i1] = packresh(p1, acc[rt][ct][2], acc[rt][ct][3]);
                } else {
                    *(float2*)&C[i0] = make_float2(acc[rt][ct][0], acc[rt][ct][1]);
                    *(float2*)&C[i1] = make_float2(acc[rt][ct][2], acc[rt][ct][3]);
                }
            }
    }
}

// ---------------------------------------------------------------------------
// Flash attention. CTA: 128 q-rows x 128 kv tile, 8 warps.
//   S = Qh*Kh + Ql*Kh   (K single fp16, Q hi/lo)
//   O = Ph*Vh           (single pass)
// ---------------------------------------------------------------------------
#define BQa 128
#define BKVa 128
#define TST 144
#define SQH 0
#define SQL (128 * TST)
#define KVB (2 * 128 * TST)
#define KVSTG (2 * 128 * TST)           // Kh + Vh
#define ATTN_SMEM (KVB + 2 * KVSTG)     // 110592 B

__global__ __launch_bounds__(256) void attn_mma(
    const __half* __restrict__ qkvh, const __half* __restrict__ qkvl,
    __half* __restrict__ oh)
{
    extern __shared__ char smem[];
    const uint32_t sb = smem_u32(smem);
    const int tid = threadIdx.x, wid = tid >> 5, lane = tid & 31;
    const int qi = (int)gridDim.x - 1 - (int)blockIdx.x;   // heavy tiles first
    const int h = blockIdx.y, b = blockIdx.z;
    const int qbase = qi * BQa;
    const int wq = wid * 16;
    const uint32_t lrow = lane & 15, lcol = (lane >> 4) * 16;
    const size_t ld = 3 * Dv;

    // Load Q tile (hi, lo)
    {
        const size_t base = ((size_t)b * Sv + qbase) * ld + (size_t)h * HDv;
        #pragma unroll
        for (int i = 0; i < 8; ++i) {
            int idx = tid + i * 256;
            int t = idx >> 10, rr = (idx >> 3) & 127, ch = idx & 7;
            const __half* src = (t ? qkvl : qkvh) + base + (size_t)rr * ld + ch * 8;
            CP_ASYNC16(sb + (t ? SQL : SQH) + rr * TST + ch * 16, src);
        }
    }

    const int ntiles = qi + 1;
    // prologue: KV tile 0 -> stage 0 (Kh, Vh from qkvh)
    {
        const size_t kbase = ((size_t)b * Sv) * ld + Dv + (size_t)h * HDv;
        #pragma unroll
        for (int i = 0; i < 8; ++i) {
            int idx = tid + i * 256;
            int t = idx >> 10, rr = (idx >> 3) & 127, ch = idx & 7;
            const __half* src = qkvh + kbase + (t ? Dv : 0) + (size_t)rr * ld + ch * 8;
            CP_ASYNC16(sb + KVB + t * (128 * TST) + rr * TST + ch * 16, src);
        }
    }
    CP_COMMIT();

    float s[16][4], o[8][4];
    #pragma unroll
    for (int t = 0; t < 8; ++t)
        #pragma unroll
        for (int e = 0; e < 4; ++e) o[t][e] = 0.f;
    float m0 = -1e30f, m1 = -1e30f, l0 = 0.f, l1 = 0.f;

    for (int j = 0; j < ntiles; ++j) {
        const int stg = j & 1;
        if (j + 1 < ntiles) {
            const size_t kbase = ((size_t)b * Sv + (size_t)(j + 1) * BKVa) * ld + Dv + (size_t)h * HDv;
            uint32_t s0 = sb + KVB + (stg ^ 1) * KVSTG;
            #pragma unroll
            for (int i = 0; i < 8; ++i) {
                int idx = tid + i * 256;
                int t = idx >> 10, rr = (idx >> 3) & 127, ch = idx & 7;
                const __half* src = qkvh + kbase + (t ? Dv : 0) + (size_t)rr * ld + ch * 8;
                CP_ASYNC16(s0 + t * (128 * TST) + rr * TST + ch * 16, src);
            }
            CP_COMMIT();
            CP_WAIT(1);
        } else {
            CP_WAIT(0);
        }
        __syncthreads();

        const uint32_t kh_b = sb + KVB + stg * KVSTG;
        const uint32_t vh_b = kh_b + 128 * TST;

        // S = Q K^T (2-pass), 16 n8-tiles
        #pragma unroll
        for (int t = 0; t < 16; ++t)
            #pragma unroll
            for (int e = 0; e < 4; ++e) s[t][e] = 0.f;
        #pragma unroll
        for (int dc = 0; dc < 4; ++dc) {
            uint32_t qoff = (wq + lrow) * TST + dc * 32 + lcol;
            uint32_t qh[4], ql[4];
            LDSM_X4(qh[0], qh[1], qh[2], qh[3], sb + SQH + qoff);
            LDSM_X4(ql[0], ql[1], ql[2], ql[3], sb + SQL + qoff);
            #pragma unroll
            for (int ng = 0; ng < 8; ++ng) {
                uint32_t koff = (ng * 16 + lrow) * TST + dc * 32 + lcol;
                uint32_t kh[4];
                LDSM_X4(kh[0], kh[1], kh[2], kh[3], kh_b + koff);
                uint32_t b0h[2] = { kh[0], kh[2] }, b1h[2] = { kh[1], kh[3] };
                MMAH(s[2 * ng],     qh, b0h);
                MMAH(s[2 * ng + 1], qh, b1h);
                MMAH(s[2 * ng],     ql, b0h);
                MMAH(s[2 * ng + 1], ql, b1h);
            }
        }

        // scale + causal mask (diagonal tile only)
        const int row0 = qbase + wq + (lane >> 2);
        if (j == ntiles - 1) {
            #pragma unroll
            for (int t = 0; t < 16; ++t) {
                int colb = j * BKVa + 8 * t + (lane & 3) * 2;
                #pragma unroll
                for (int e = 0; e < 4; ++e) {
                    int col = colb + (e & 1);
                    int row = (e < 2) ? row0 : row0 + 8;
                    s[t][e] = (col > row) ? -1e30f : s[t][e] * 0.125f;
                }
            }
        } else {
            #pragma unroll
            for (int t = 0; t < 16; ++t)
                #pragma unroll
                for (int e = 0; e < 4; ++e) s[t][e] *= 0.125f;
        }

        // online softmax
        float mx0 = -1e30f, mx1 = -1e30f;
        #pragma unroll
        for (int t = 0; t < 16; ++t) {
            mx0 = fmaxf(mx0, fmaxf(s[t][0], s[t][1]));
            mx1 = fmaxf(mx1, fmaxf(s[t][2], s[t][3]));
        }
        mx0 = fmaxf(mx0, __shfl_xor_sync(0xffffffffu, mx0, 1));
        mx0 = fmaxf(mx0, __shfl_xor_sync(0xffffffffu, mx0, 2));
        mx1 = fmaxf(mx1, __shfl_xor_sync(0xffffffffu, mx1, 1));
        mx1 = fmaxf(mx1, __shfl_xor_sync(0xffffffffu, mx1, 2));
        float mn0 = fmaxf(m0, mx0), mn1 = fmaxf(m1, mx1);
        float a0 = __expf(m0 - mn0), a1 = __expf(m1 - mn1);
        m0 = mn0; m1 = mn1;
        float rs0 = 0.f, rs1 = 0.f;
        #pragma unroll
        for (int t = 0; t < 16; ++t) {
            s[t][0] = __expf(s[t][0] - mn0);
            s[t][1] = __expf(s[t][1] - mn0);
            s[t][2] = __expf(s[t][2] - mn1);
            s[t][3] = __expf(s[t][3] - mn1);
            rs0 += s[t][0] + s[t][1];
            rs1 += s[t][2] + s[t][3];
        }
        #pragma unroll
        for (int t = 0; t < 8; ++t) {
            o[t][0] *= a0; o[t][1] *= a0; o[t][2] *= a1; o[t][3] *= a1;
        }
        rs0 += __shfl_xor_sync(0xffffffffu, rs0, 1);
        rs0 += __shfl_xor_sync(0xffffffffu, rs0, 2);
        rs1 += __shfl_xor_sync(0xffffffffu, rs1, 1);
        rs1 += __shfl_xor_sync(0xffffffffu, rs1, 2);
        l0 = l0 * a0 + rs0;
        l1 = l1 * a1 + rs1;

        // O += P V (single pass: Ph*Vh)
        #pragma unroll
        for (int kc = 0; kc < 8; ++kc) {
            uint32_t pah[4];
            pah[0] = packh(s[2 * kc][0], s[2 * kc][1]);
            pah[1] = packh(s[2 * kc][2], s[2 * kc][3]);
            pah[2] = packh(s[2 * kc + 1][0], s[2 * kc + 1][1]);
            pah[3] = packh(s[2 * kc + 1][2], s[2 * kc + 1][3]);
            #pragma unroll
            for (int ng = 0; ng < 4; ++ng) {
                uint32_t voff = (kc * 16 + lrow) * TST + ng * 32 + lcol;
                uint32_t vh[4];
                LDSM_X4_T(vh[0], vh[1], vh[2], vh[3], vh_b + voff);
                uint32_t bv0[2] = { vh[0], vh[1] }, bv1[2] = { vh[2], vh[3] };
                MMAH(o[2 * ng],     pah, bv0);
                MMAH(o[2 * ng + 1], pah, bv1);
            }
        }
        __syncthreads();
    }

    // epilogue: O/l -> fp16 at [b*S + q][h*64 + n]
    const float i0 = 1.f / l0, i1 = 1.f / l1;
    const size_t r0 = (size_t)b * Sv + qbase + wq + (lane >> 2);
    const int cb = h * HDv + (lane & 3) * 2;
    #pragma unroll
    for (int t = 0; t < 8; ++t) {
        size_t ia = r0 * Dv + cb + 8 * t;
        size_t ib = ia + (size_t)8 * Dv;
        *(uint32_t*)&oh[ia] = packh(o[t][0] * i0, o[t][1] * i0);
        *(uint32_t*)&oh[ib] = packh(o[t][2] * i1, o[t][3] * i1);
    }
}

// ---------------------------------------------------------------------------
extern "C" void kernel_launch(void* const* d_in, const int* in_sizes, int n_in,
                              void* d_out, int out_size)
{
    (void)in_sizes; (void)n_in; (void)out_size;
    const float* x     = (const float*)d_in[0];
    const float* w_qkv = (const float*)d_in[1];
    const float* w_out = (const float*)d_in[2];
    float* out = (float*)d_out;

    __half *xh, *wq, *qkvh, *qkvl, *oh, *wo;
    cudaGetSymbolAddress((void**)&xh, g_xh);
    cudaGetSymbolAddress((void**)&wq, g_wq);
    cudaGetSymbolAddress((void**)&qkvh, g_qkvh); cudaGetSymbolAddress((void**)&qkvl, g_qkvl);
    cudaGetSymbolAddress((void**)&oh, g_oh);
    cudaGetSymbolAddress((void**)&wo, g_wo);

    cudaFuncSetAttribute(attn_mma,
                         cudaFuncAttributeMaxDynamicSharedMemorySize, ATTN_SMEM);
    cudaFuncSetAttribute(gemm_mma_h<1, 1>,
                         cudaFuncAttributeMaxDynamicSharedMemorySize, GEMM_SMEM);
    cudaFuncSetAttribute(gemm_mma_h<0, 1>,
                         cudaFuncAttributeMaxDynamicSharedMemorySize, GEMM_SMEM);

    // Conversions (all single fp16 now)
    {
        int n4 = (Mv * Dv) / 4;
        cvt_h<<<(n4 + 255) / 256, 256>>>(x, xh, n4);
        n4 = (3 * Dv * Dv) / 4;
        cvt_h<<<(n4 + 255) / 256, 256>>>(w_qkv, wq, n4);
        n4 = (Dv * Dv) / 4;
        cvt_h<<<(n4 + 255) / 256, 256>>>(w_out, wo, n4);
    }

    // 1) QKV projection (single-pass fp16) -> fp16 hi/lo qkv
    gemm_mma_h<1, 1><<<GEMM_GRID, 128, GEMM_SMEM>>>(
        xh, nullptr, wq, nullptr, qkvh, qkvl, Mv, Dv, 3 * Dv);

    // 2) Causal flash attention (2-pass QK, 1-pass PV) -> fp16 O
    {
        dim3 g(Sv / BQa, Hv, Bv);
        attn_mma<<<g, 256, ATTN_SMEM>>>(qkvh, qkvl, oh);
    }

    // 3) Output projection (1-pass fp16) -> fp32 out
    gemm_mma_h<0, 1><<<GEMM_GRID, 128, GEMM_SMEM>>>(
        oh, nullptr, wo, out, nullptr, nullptr, Mv, Dv, Dv);
}

// round 13
// speedup vs baseline: 2.4145x; 1.1226x over previous
#include <cuda_runtime.h>
#include <cuda_fp16.h>
#include <math.h>
#include <stdint.h>

// Problem constants
#define Bv 2
#define Sv 2048
#define Dv 1024
#define Hv 16
#define HDv 64
#define Mv (Bv*Sv)   // 4096 rows

// ---------------------------------------------------------------------------
// Scratch (device globals: no allocation allowed)
// ---------------------------------------------------------------------------
__device__ __align__(16) __half g_xh[(size_t)Mv * Dv];
__device__ __align__(16) __half g_wq[(size_t)3 * Dv * Dv];
__device__ __align__(16) __half g_qkvh[(size_t)Mv * 3 * Dv];
__device__ __align__(16) __half g_oh[(size_t)Mv * Dv];
__device__ __align__(16) __half g_wo[(size_t)Dv * Dv];

// ---------------------------------------------------------------------------
// PTX helpers
// ---------------------------------------------------------------------------
__device__ __forceinline__ uint32_t smem_u32(const void* p) {
    uint32_t a;
    asm("{ .reg .u64 t; cvta.to.shared.u64 t, %1; cvt.u32.u64 %0, t; }" : "=r"(a) : "l"(p));
    return a;
}
#define CP_ASYNC16(sm, g) \
    asm volatile("cp.async.cg.shared.global [%0], [%1], 16;" :: "r"(sm), "l"(g) : "memory")
#define CP_COMMIT() asm volatile("cp.async.commit_group;" ::: "memory")
#define CP_WAIT(n)  asm volatile("cp.async.wait_group %0;" :: "n"(n) : "memory")

#define LDSM_X4(r0, r1, r2, r3, addr) \
    asm volatile("ldmatrix.sync.aligned.m8n8.x4.shared.b16 {%0,%1,%2,%3}, [%4];" \
        : "=r"(r0), "=r"(r1), "=r"(r2), "=r"(r3) : "r"(addr))
#define LDSM_X4_T(r0, r1, r2, r3, addr) \
    asm volatile("ldmatrix.sync.aligned.m8n8.x4.trans.shared.b16 {%0,%1,%2,%3}, [%4];" \
        : "=r"(r0), "=r"(r1), "=r"(r2), "=r"(r3) : "r"(addr))

// fp16 mma, fp32 accumulate
#define MMAH(d, a, b) \
    asm volatile("mma.sync.aligned.m16n8k16.row.col.f32.f16.f16.f32 " \
        "{%0,%1,%2,%3}, {%4,%5,%6,%7}, {%8,%9}, {%0,%1,%2,%3};" \
        : "+f"((d)[0]), "+f"((d)[1]), "+f"((d)[2]), "+f"((d)[3]) \
        : "r"((a)[0]), "r"((a)[1]), "r"((a)[2]), "r"((a)[3]), "r"((b)[0]), "r"((b)[1]))

// pack(lo, hi) -> f16x2 register (lo in low 16 bits)
__device__ __forceinline__ uint32_t packh(float lo, float hi) {
    __half2 h = __floats2half2_rn(lo, hi);
    return *reinterpret_cast<uint32_t*>(&h);
}

// ---------------------------------------------------------------------------
// fp32 -> fp16 (single)
// ---------------------------------------------------------------------------
__global__ __launch_bounds__(256) void cvt_h(
    const float* __restrict__ in, __half* __restrict__ out, int n4)
{
    int i = blockIdx.x * blockDim.x + threadIdx.x;
    if (i >= n4) return;
    float4 v = ((const float4*)in)[i];
    ((uint2*)out)[i] = make_uint2(packh(v.x, v.y), packh(v.z, v.w));
}

// ---------------------------------------------------------------------------
// Persistent single-pass fp16 GEMM:  C[M,N] = A[M,K] * B[N,K]^T
// 128x128x32 CTA tile, 128 threads = 4 warps (64x64 each).
// 3-stage cp.async pipeline (hides load latency at high load:MMA ratio).
// WB=1: write fp16; WB=0: write fp32.
// ---------------------------------------------------------------------------
#define BM 128
#define BN 128
#define BKc 32
#define TILE_BYT (128 * 80)           // 80B row stride
#define STAGE_BYT (2 * TILE_BYT)      // A, B
#define GEMM_SMEM (3 * STAGE_BYT)     // 61440 B
#define GEMM_GRID 296

__device__ __forceinline__ void load_stage(
    uint32_t sb, int s,
    const __half* __restrict__ A, const __half* __restrict__ B,
    int bm, int bn, int k0, int K, int tid)
{
    uint32_t base = sb + s * STAGE_BYT;
    #pragma unroll
    for (int j = 0; j < 4; ++j) {
        int idx = tid + j * 128;            // 0..511
        int row = idx >> 2, ch = idx & 3;
        CP_ASYNC16(base + row * 80 + ch * 16,
                   A + (size_t)(bm + row) * K + k0 + ch * 8);
        CP_ASYNC16(base + TILE_BYT + row * 80 + ch * 16,
                   B + (size_t)(bn + row) * K + k0 + ch * 8);
    }
}

template<int WB>
__global__ __launch_bounds__(128) void gemm_mma_h(
    const __half* __restrict__ A, const __half* __restrict__ B,
    float* __restrict__ C, __half* __restrict__ Ch, int M, int K, int N)
{
    extern __shared__ char smem[];
    const uint32_t sb = smem_u32(smem);
    const int tid = threadIdx.x, wid = tid >> 5, lane = tid & 31;
    const int wm = (wid >> 1) * 64;
    const int wn = (wid & 1) * 64;
    const uint32_t lrow = (lane & 15);
    const uint32_t lcol = (lane >> 4) * 16;
    const int ntn = N / BN;
    const int ntot = (M / BM) * ntn;
    const int NKB = K / BKc;              // 32

    for (int tix = blockIdx.x; tix < ntot; tix += (int)gridDim.x) {
        const int bm = (tix / ntn) * BM, bn = (tix % ntn) * BN;

        float acc[4][8][4];
        #pragma unroll
        for (int i = 0; i < 4; ++i)
            #pragma unroll
            for (int j = 0; j < 8; ++j)
                #pragma unroll
                for (int q = 0; q < 4; ++q) acc[i][j][q] = 0.f;

        load_stage(sb, 0, A, B, bm, bn, 0, K, tid);
        CP_COMMIT();
        load_stage(sb, 1, A, B, bm, bn, BKc, K, tid);
        CP_COMMIT();

        for (int kb = 0; kb < NKB; ++kb) {
            const int s = kb % 3;
            if (kb + 2 < NKB) {
                // stage being filled == stage read at iter kb-1; protected by
                // the trailing __syncthreads of that iteration.
                load_stage(sb, (kb + 2) % 3, A, B, bm, bn, (kb + 2) * BKc, K, tid);
                CP_COMMIT();
                CP_WAIT(2);
            } else if (kb + 1 < NKB) {
                CP_WAIT(1);
            } else {
                CP_WAIT(0);
            }
            __syncthreads();

            const uint32_t stb = sb + s * STAGE_BYT;
            #pragma unroll
            for (int ks = 0; ks < 2; ++ks) {
                const uint32_t koff = ks * 32 + lcol;
                uint32_t aa[4][4], bb[4][4];
                #pragma unroll
                for (int rt = 0; rt < 4; ++rt) {
                    uint32_t ro = (wm + rt * 16 + lrow) * 80 + koff;
                    LDSM_X4(aa[rt][0], aa[rt][1], aa[rt][2], aa[rt][3], stb + ro);
                }
                #pragma unroll
                for (int g = 0; g < 4; ++g) {
                    uint32_t ro = (wn + g * 16 + lrow) * 80 + koff;
                    LDSM_X4(bb[g][0], bb[g][1], bb[g][2], bb[g][3], stb + TILE_BYT + ro);
                }
                #pragma unroll
                for (int rt = 0; rt < 4; ++rt)
                    #pragma unroll
                    for (int g = 0; g < 4; ++g)
                        #pragma unroll
                        for (int sub = 0; sub < 2; ++sub) {
                            uint32_t bf[2] = { bb[g][sub], bb[g][sub + 2] };
                            MMAH(acc[rt][g * 2 + sub], aa[rt], bf);
                        }
            }
            __syncthreads();
        }

        const int r0 = bm + wm + (lane >> 2);
        const int c0 = bn + wn + (lane & 3) * 2;
        #pragma unroll
        for (int rt = 0; rt < 4; ++rt)
            #pragma unroll
            for (int ct = 0; ct < 8; ++ct) {
                size_t i0 = (size_t)(r0 + rt * 16) * N + c0 + ct * 8;
                size_t i1 = i0 + (size_t)8 * N;
                if (WB) {
                    *(uint32_t*)&Ch[i0] = packh(acc[rt][ct][0], acc[rt][ct][1]);
                    *(uint32_t*)&Ch[i1] = packh(acc[rt][ct][2], acc[rt][ct][3]);
                } else {
                    *(float2*)&C[i0] = make_float2(acc[rt][ct][0], acc[rt][ct][1]);
                    *(float2*)&C[i1] = make_float2(acc[rt][ct][2], acc[rt][ct][3]);
                }
            }
    }
}

// ---------------------------------------------------------------------------
// Flash attention, all single-pass fp16. CTA: 128 q-rows x 128 kv tile.
//   S = Qh*Kh ; O = Ph*Vh
// ---------------------------------------------------------------------------
#define BQa 128
#define BKVa 128
#define TST 144
#define SQH 0
#define KVB (128 * TST)
#define KVSTG (2 * 128 * TST)           // Kh + Vh
#define ATTN_SMEM (KVB + 2 * KVSTG)     // 92160 B

__global__ __launch_bounds__(256) void attn_mma(
    const __half* __restrict__ qkvh, __half* __restrict__ oh)
{
    extern __shared__ char smem[];
    const uint32_t sb = smem_u32(smem);
    const int tid = threadIdx.x, wid = tid >> 5, lane = tid & 31;
    const int qi = (int)gridDim.x - 1 - (int)blockIdx.x;   // heavy tiles first
    const int h = blockIdx.y, b = blockIdx.z;
    const int qbase = qi * BQa;
    const int wq = wid * 16;
    const uint32_t lrow = lane & 15, lcol = (lane >> 4) * 16;
    const size_t ld = 3 * Dv;

    // Load Q tile
    {
        const size_t base = ((size_t)b * Sv + qbase) * ld + (size_t)h * HDv;
        #pragma unroll
        for (int i = 0; i < 4; ++i) {
            int idx = tid + i * 256;            // 128 rows * 8 chunks
            int rr = (idx >> 3) & 127, ch = idx & 7;
            CP_ASYNC16(sb + SQH + rr * TST + ch * 16,
                       qkvh + base + (size_t)rr * ld + ch * 8);
        }
    }

    const int ntiles = qi + 1;
    // prologue: KV tile 0 -> stage 0 (Kh, Vh)
    {
        const size_t kbase = ((size_t)b * Sv) * ld + Dv + (size_t)h * HDv;
        #pragma unroll
        for (int i = 0; i < 8; ++i) {
            int idx = tid + i * 256;
            int t = idx >> 10, rr = (idx >> 3) & 127, ch = idx & 7;
            const __half* src = qkvh + kbase + (t ? Dv : 0) + (size_t)rr * ld + ch * 8;
            CP_ASYNC16(sb + KVB + t * (128 * TST) + rr * TST + ch * 16, src);
        }
    }
    CP_COMMIT();

    float s[16][4], o[8][4];
    #pragma unroll
    for (int t = 0; t < 8; ++t)
        #pragma unroll
        for (int e = 0; e < 4; ++e) o[t][e] = 0.f;
    float m0 = -1e30f, m1 = -1e30f, l0 = 0.f, l1 = 0.f;

    for (int j = 0; j < ntiles; ++j) {
        const int stg = j & 1;
        if (j + 1 < ntiles) {
            const size_t kbase = ((size_t)b * Sv + (size_t)(j + 1) * BKVa) * ld + Dv + (size_t)h * HDv;
            uint32_t s0 = sb + KVB + (stg ^ 1) * KVSTG;
            #pragma unroll
            for (int i = 0; i < 8; ++i) {
                int idx = tid + i * 256;
                int t = idx >> 10, rr = (idx >> 3) & 127, ch = idx & 7;
                const __half* src = qkvh + kbase + (t ? Dv : 0) + (size_t)rr * ld + ch * 8;
                CP_ASYNC16(s0 + t * (128 * TST) + rr * TST + ch * 16, src);
            }
            CP_COMMIT();
            CP_WAIT(1);
        } else {
            CP_WAIT(0);
        }
        __syncthreads();

        const uint32_t kh_b = sb + KVB + stg * KVSTG;
        const uint32_t vh_b = kh_b + 128 * TST;

        // S = Q K^T (single pass), 16 n8-tiles
        #pragma unroll
        for (int t = 0; t < 16; ++t)
            #pragma unroll
            for (int e = 0; e < 4; ++e) s[t][e] = 0.f;
        #pragma unroll
        for (int dc = 0; dc < 4; ++dc) {
            uint32_t qoff = (wq + lrow) * TST + dc * 32 + lcol;
            uint32_t qh[4];
            LDSM_X4(qh[0], qh[1], qh[2], qh[3], sb + SQH + qoff);
            #pragma unroll
            for (int ng = 0; ng < 8; ++ng) {
                uint32_t koff = (ng * 16 + lrow) * TST + dc * 32 + lcol;
                uint32_t kh[4];
                LDSM_X4(kh[0], kh[1], kh[2], kh[3], kh_b + koff);
                uint32_t b0h[2] = { kh[0], kh[2] }, b1h[2] = { kh[1], kh[3] };
                MMAH(s[2 * ng],     qh, b0h);
                MMAH(s[2 * ng + 1], qh, b1h);
            }
        }

        // scale + causal mask (diagonal tile only)
        const int row0 = qbase + wq + (lane >> 2);
        if (j == ntiles - 1) {
            #pragma unroll
            for (int t = 0; t < 16; ++t) {
                int colb = j * BKVa + 8 * t + (lane & 3) * 2;
                #pragma unroll
                for (int e = 0; e < 4; ++e) {
                    int col = colb + (e & 1);
                    int row = (e < 2) ? row0 : row0 + 8;
                    s[t][e] = (col > row) ? -1e30f : s[t][e] * 0.125f;
                }
            }
        } else {
            #pragma unroll
            for (int t = 0; t < 16; ++t)
                #pragma unroll
                for (int e = 0; e < 4; ++e) s[t][e] *= 0.125f;
        }

        // online softmax
        float mx0 = -1e30f, mx1 = -1e30f;
        #pragma unroll
        for (int t = 0; t < 16; ++t) {
            mx0 = fmaxf(mx0, fmaxf(s[t][0], s[t][1]));
            mx1 = fmaxf(mx1, fmaxf(s[t][2], s[t][3]));
        }
        mx0 = fmaxf(mx0, __shfl_xor_sync(0xffffffffu, mx0, 1));
        mx0 = fmaxf(mx0, __shfl_xor_sync(0xffffffffu, mx0, 2));
        mx1 = fmaxf(mx1, __shfl_xor_sync(0xffffffffu, mx1, 1));
        mx1 = fmaxf(mx1, __shfl_xor_sync(0xffffffffu, mx1, 2));
        float mn0 = fmaxf(m0, mx0), mn1 = fmaxf(m1, mx1);
        float a0 = __expf(m0 - mn0), a1 = __expf(m1 - mn1);
        m0 = mn0; m1 = mn1;
        float rs0 = 0.f, rs1 = 0.f;
        #pragma unroll
        for (int t = 0; t < 16; ++t) {
            s[t][0] = __expf(s[t][0] - mn0);
            s[t][1] = __expf(s[t][1] - mn0);
            s[t][2] = __expf(s[t][2] - mn1);
            s[t][3] = __expf(s[t][3] - mn1);
            rs0 += s[t][0] + s[t][1];
            rs1 += s[t][2] + s[t][3];
        }
        #pragma unroll
        for (int t = 0; t < 8; ++t) {
            o[t][0] *= a0; o[t][1] *= a0; o[t][2] *= a1; o[t][3] *= a1;
        }
        rs0 += __shfl_xor_sync(0xffffffffu, rs0, 1);
        rs0 += __shfl_xor_sync(0xffffffffu, rs0, 2);
        rs1 += __shfl_xor_sync(0xffffffffu, rs1, 1);
        rs1 += __shfl_xor_sync(0xffffffffu, rs1, 2);
        l0 = l0 * a0 + rs0;
        l1 = l1 * a1 + rs1;

        // O += P V (single pass)
        #pragma unroll
        for (int kc = 0; kc < 8; ++kc) {
            uint32_t pah[4];
            pah[0] = packh(s[2 * kc][0], s[2 * kc][1]);
            pah[1] = packh(s[2 * kc][2], s[2 * kc][3]);
            pah[2] = packh(s[2 * kc + 1][0], s[2 * kc + 1][1]);
            pah[3] = packh(s[2 * kc + 1][2], s[2 * kc + 1][3]);
            #pragma unroll
            for (int ng = 0; ng < 4; ++ng) {
                uint32_t voff = (kc * 16 + lrow) * TST + ng * 32 + lcol;
                uint32_t vh[4];
                LDSM_X4_T(vh[0], vh[1], vh[2], vh[3], vh_b + voff);
                uint32_t bv0[2] = { vh[0], vh[1] }, bv1[2] = { vh[2], vh[3] };
                MMAH(o[2 * ng],     pah, bv0);
                MMAH(o[2 * ng + 1], pah, bv1);
            }
        }
        __syncthreads();
    }

    // epilogue: O/l -> fp16 at [b*S + q][h*64 + n]
    const float i0 = 1.f / l0, i1 = 1.f / l1;
    const size_t r0 = (size_t)b * Sv + qbase + wq + (lane >> 2);
    const int cb = h * HDv + (lane & 3) * 2;
    #pragma unroll
    for (int t = 0; t < 8; ++t) {
        size_t ia = r0 * Dv + cb + 8 * t;
        size_t ib = ia + (size_t)8 * Dv;
        *(uint32_t*)&oh[ia] = packh(o[t][0] * i0, o[t][1] * i0);
        *(uint32_t*)&oh[ib] = packh(o[t][2] * i1, o[t][3] * i1);
    }
}

// ---------------------------------------------------------------------------
extern "C" void kernel_launch(void* const* d_in, const int* in_sizes, int n_in,
                              void* d_out, int out_size)
{
    (void)in_sizes; (void)n_in; (void)out_size;
    const float* x     = (const float*)d_in[0];
    const float* w_qkv = (const float*)d_in[1];
    const float* w_out = (const float*)d_in[2];
    float* out = (float*)d_out;

    __half *xh, *wq, *qkvh, *oh, *wo;
    cudaGetSymbolAddress((void**)&xh, g_xh);
    cudaGetSymbolAddress((void**)&wq, g_wq);
    cudaGetSymbolAddress((void**)&qkvh, g_qkvh);
    cudaGetSymbolAddress((void**)&oh, g_oh);
    cudaGetSymbolAddress((void**)&wo, g_wo);

    cudaFuncSetAttribute(attn_mma,
                         cudaFuncAttributeMaxDynamicSharedMemorySize, ATTN_SMEM);
    cudaFuncSetAttribute(gemm_mma_h<1>,
                         cudaFuncAttributeMaxDynamicSharedMemorySize, GEMM_SMEM);
    cudaFuncSetAttribute(gemm_mma_h<0>,
                         cudaFuncAttributeMaxDynamicSharedMemorySize, GEMM_SMEM);

    // Conversions (all single fp16)
    {
        int n4 = (Mv * Dv) / 4;
        cvt_h<<<(n4 + 255) / 256, 256>>>(x, xh, n4);
        n4 = (3 * Dv * Dv) / 4;
        cvt_h<<<(n4 + 255) / 256, 256>>>(w_qkv, wq, n4);
        n4 = (Dv * Dv) / 4;
        cvt_h<<<(n4 + 255) / 256, 256>>>(w_out, wo, n4);
    }

    // 1) QKV projection (single-pass fp16, 3-stage pipe) -> fp16 qkv
    gemm_mma_h<1><<<GEMM_GRID, 128, GEMM_SMEM>>>(
        xh, wq, nullptr, qkvh, Mv, Dv, 3 * Dv);

    // 2) Causal flash attention (1-pass QK, 1-pass PV) -> fp16 O
    {
        dim3 g(Sv / BQa, Hv, Bv);
        attn_mma<<<g, 256, ATTN_SMEM>>>(qkvh, oh);
    }

    // 3) Output projection (1-pass fp16, 3-stage pipe) -> fp32 out
    gemm_mma_h<0><<<GEMM_GRID, 128, GEMM_SMEM>>>(
        oh, wo, out, nullptr, Mv, Dv, Dv);
}